// round 1
// baseline (speedup 1.0000x reference)
#include <cuda_runtime.h>
#include <math.h>

// Problem constants
#define Bn 2
#define Tn 1024
#define Cn 2048
#define Hn 32
#define Nn 64
#define BTn (Bn*Tn)

// ------------------------- scratch (static device globals) -------------------------
__device__ float g_xr[BTn*Cn];
__device__ float g_xw[BTn*Cn];
__device__ float g_xk[BTn*Cn];
__device__ float g_xv[BTn*Cn];
__device__ float g_xa[BTn*Cn];
__device__ float g_xg[BTn*Cn];
__device__ float g_r [BTn*Cn];
__device__ float g_k [BTn*Cn];
__device__ float g_v [BTn*Cn];
__device__ float g_w [BTn*Cn];   // holds w_lora, then decay (in place)
__device__ float g_za[BTn*Cn];
__device__ float g_zv[BTn*Cn];
__device__ float g_g [BTn*Cn];
__device__ float g_ah[BTn*Cn];
__device__ float g_bh[BTn*Cn];
__device__ float g_y [BTn*Cn];
__device__ float g_op[BTn*Cn];
__device__ float g_tw[BTn*96];
__device__ float g_ta[BTn*96];
__device__ float g_tv[BTn*64];
__device__ float g_tg[BTn*256];

// ------------------------- tiled SGEMM: C[M,N] = A[M,K] @ B[K,N] -------------------
// M must be a multiple of 128 (always 2048 here). N arbitrary. K multiple of 8.
// ACT: 0=none, 1=tanh, 2=sigmoid (applied to output)
template<int ACT>
__global__ void __launch_bounds__(256) sgemm_k(const float* __restrict__ A,
                                               const float* __restrict__ B,
                                               float* __restrict__ C,
                                               int M, int N, int K) {
    __shared__ float As[8][128];
    __shared__ float Bs[8][128];
    const int bm = blockIdx.y * 128;
    const int bn = blockIdx.x * 128;
    const int tid = threadIdx.x;
    const int tr = tid >> 4;   // 0..15
    const int tc = tid & 15;   // 0..15

    float acc[8][8];
#pragma unroll
    for (int i = 0; i < 8; i++)
#pragma unroll
        for (int j = 0; j < 8; j++) acc[i][j] = 0.f;

    const int lam = tid >> 1;          // 0..127 (A row within tile)
    const int lak = (tid & 1) * 4;     // 0 or 4 (A k quad)
    const int lbk = tid >> 5;          // 0..7 (B k row)
    const int lbn = (tid & 31) * 4;    // 0..124 (B col quad)

    for (int k0 = 0; k0 < K; k0 += 8) {
        float4 av = *(const float4*)(A + (size_t)(bm + lam) * K + k0 + lak);
        As[lak + 0][lam] = av.x;
        As[lak + 1][lam] = av.y;
        As[lak + 2][lam] = av.z;
        As[lak + 3][lam] = av.w;
        if (bn + lbn + 3 < N) {
            float4 bv = *(const float4*)(B + (size_t)(k0 + lbk) * N + bn + lbn);
            Bs[lbk][lbn + 0] = bv.x;
            Bs[lbk][lbn + 1] = bv.y;
            Bs[lbk][lbn + 2] = bv.z;
            Bs[lbk][lbn + 3] = bv.w;
        } else {
#pragma unroll
            for (int j = 0; j < 4; j++) {
                int n = bn + lbn + j;
                Bs[lbk][lbn + j] = (n < N) ? B[(size_t)(k0 + lbk) * N + n] : 0.f;
            }
        }
        __syncthreads();
#pragma unroll
        for (int k = 0; k < 8; k++) {
            float a[8], b[8];
            float4 t0 = *(const float4*)&As[k][tr * 8];
            float4 t1 = *(const float4*)&As[k][tr * 8 + 4];
            a[0]=t0.x; a[1]=t0.y; a[2]=t0.z; a[3]=t0.w;
            a[4]=t1.x; a[5]=t1.y; a[6]=t1.z; a[7]=t1.w;
            float4 u0 = *(const float4*)&Bs[k][tc * 8];
            float4 u1 = *(const float4*)&Bs[k][tc * 8 + 4];
            b[0]=u0.x; b[1]=u0.y; b[2]=u0.z; b[3]=u0.w;
            b[4]=u1.x; b[5]=u1.y; b[6]=u1.z; b[7]=u1.w;
#pragma unroll
            for (int i = 0; i < 8; i++)
#pragma unroll
                for (int j = 0; j < 8; j++)
                    acc[i][j] = fmaf(a[i], b[j], acc[i][j]);
        }
        __syncthreads();
    }

#pragma unroll
    for (int i = 0; i < 8; i++) {
        int m = bm + tr * 8 + i;
#pragma unroll
        for (int j = 0; j < 8; j++) {
            int n = bn + tc * 8 + j;
            if (n < N) {
                float v = acc[i][j];
                if (ACT == 1) v = tanhf(v);
                if (ACT == 2) v = 1.f / (1.f + expf(-v));
                C[(size_t)m * N + n] = v;
            }
        }
    }
}

// ------------------------- token shift + 6 mixes -------------------------
__global__ void mix_kernel(const float* __restrict__ x,
                           const float* __restrict__ cr, const float* __restrict__ cw,
                           const float* __restrict__ ck, const float* __restrict__ cv,
                           const float* __restrict__ ca, const float* __restrict__ cg) {
    size_t i = (size_t)blockIdx.x * blockDim.x + threadIdx.x;
    if (i >= (size_t)BTn * Cn) return;
    int c = (int)(i % Cn);
    size_t bt = i / Cn;
    int t = (int)(bt % Tn);
    float xc = x[i];
    float prev = (t == 0) ? 0.f : x[i - Cn];
    float dx = prev - xc;
    g_xr[i] = xc + dx * cr[c];
    g_xw[i] = xc + dx * cw[c];
    g_xk[i] = xc + dx * ck[c];
    g_xv[i] = xc + dx * cv[c];
    g_xa[i] = xc + dx * ca[c];
    g_xg[i] = xc + dx * cg[c];
}

// ------------------------- per-head elementwise stage 2 -------------------------
// decay, ICLR a, v-mix, k modification, normalized kk -> ah/bh
__global__ void ew2_kernel(const float* __restrict__ w0, const float* __restrict__ a0,
                           const float* __restrict__ v0, const float* __restrict__ kkw,
                           const float* __restrict__ kaw, const float* __restrict__ vfirst) {
    int bt = blockIdx.x / Hn;
    int h  = blockIdx.x % Hn;
    int n  = threadIdx.x;          // 0..63
    int c  = h * Nn + n;
    size_t idx = (size_t)bt * Cn + c;

    __shared__ float red[64];
    float kraw = g_k[idx];
    float kkp = kraw * kkw[c];
    red[n] = kkp * kkp;
    __syncthreads();
#pragma unroll
    for (int s = 32; s > 0; s >>= 1) { if (n < s) red[n] += red[n + s]; __syncthreads(); }
    float norm = sqrtf(red[0]);
    float kkn = kkp / fmaxf(norm, 1e-12f);

    float av = 1.f / (1.f + expf(-(a0[c] + g_za[idx])));
    float xw = -(w0[c] + g_w[idx]);
    float sp = (xw > 20.f) ? xw : log1pf(expf(xw));     // softplus(-(w0+w_lora))
    float wv = expf(-expf(-0.5f - sp));
    float vs = 1.f / (1.f + expf(-(v0[c] + g_zv[idx])));
    float vraw = g_v[idx];
    float vv = vraw + (vfirst[idx] - vraw) * vs;

    g_w[idx]  = wv;
    g_k[idx]  = kraw * (1.f + (av - 1.f) * kaw[c]);
    g_v[idx]  = vv;
    g_ah[idx] = -kkn;
    g_bh[idx] = kkn * av;
}

// ------------------------- WKV7 sequential scan -------------------------
// grid = B*H blocks; 256 threads; thread (v=tid>>2, kq=tid&3) owns S[v][16*kq..16*kq+15]
__global__ void __launch_bounds__(256) wkv7_scan() {
    int bh = blockIdx.x;
    int b = bh / Hn, h = bh % Hn;
    int tid = threadIdx.x;
    int v = tid >> 2;
    int kq = tid & 3;

    float S[16];
#pragma unroll
    for (int i = 0; i < 16; i++) S[i] = 0.f;

    __shared__ float sm[6][64]; // r, w, k, v, ah, bh
    size_t base = (size_t)b * Tn * Cn + (size_t)h * Nn;

    for (int t = 0; t < Tn; t++) {
        size_t off = base + (size_t)t * Cn;
        {
            int nn = tid & 63;
            int arr = tid >> 6;  // 0..3
            float val = (arr == 0) ? g_r[off + nn]
                      : (arr == 1) ? g_w[off + nn]
                      : (arr == 2) ? g_k[off + nn]
                                   : g_v[off + nn];
            sm[arr][nn] = val;
            if (tid < 128) {
                sm[4 + (tid >> 6)][nn] = (tid < 64) ? g_ah[off + nn] : g_bh[off + nn];
            }
        }
        __syncthreads();

        float sa = 0.f;
#pragma unroll
        for (int i = 0; i < 16; i++) sa = fmaf(S[i], sm[4][kq * 16 + i], sa);
        sa += __shfl_xor_sync(0xffffffffu, sa, 1);
        sa += __shfl_xor_sync(0xffffffffu, sa, 2);

        float vv = sm[3][v];
        float y = 0.f;
#pragma unroll
        for (int i = 0; i < 16; i++) {
            int kk = kq * 16 + i;
            S[i] = fmaf(S[i], sm[1][kk], fmaf(sa, sm[5][kk], vv * sm[2][kk]));
            y = fmaf(S[i], sm[0][kk], y);
        }
        y += __shfl_xor_sync(0xffffffffu, y, 1);
        y += __shfl_xor_sync(0xffffffffu, y, 2);
        if (kq == 0) g_y[off + v] = y;
        __syncthreads();
    }
}

// ------------------------- groupnorm + rk residual + gate -------------------------
__global__ void gn_kernel(const float* __restrict__ r_k, const float* __restrict__ gnw,
                          const float* __restrict__ gnb) {
    int bt = blockIdx.x / Hn;
    int h  = blockIdx.x % Hn;
    int n  = threadIdx.x;
    int c  = h * Nn + n;
    size_t idx = (size_t)bt * Cn + c;

    __shared__ float red[64];
    float yv = g_y[idx];
    red[n] = yv;
    __syncthreads();
#pragma unroll
    for (int s = 32; s > 0; s >>= 1) { if (n < s) red[n] += red[n + s]; __syncthreads(); }
    float mu = red[0] * (1.f / 64.f);
    __syncthreads();

    float d = yv - mu;
    red[n] = d * d;
    __syncthreads();
#pragma unroll
    for (int s = 32; s > 0; s >>= 1) { if (n < s) red[n] += red[n + s]; __syncthreads(); }
    float var = red[0] * (1.f / 64.f);
    __syncthreads();

    float yn = d * rsqrtf(var + (float)(Nn * 1e-5)) * gnw[c] + gnb[c];

    float dp = g_r[idx] * g_k[idx] * r_k[c];   // r_k[H,N] flat index == c
    red[n] = dp;
    __syncthreads();
#pragma unroll
    for (int s = 32; s > 0; s >>= 1) { if (n < s) red[n] += red[n + s]; __syncthreads(); }
    float dot = red[0];

    g_op[idx] = (yn + dot * g_v[idx]) * g_g[idx];
}

// ------------------------- launch -------------------------
extern "C" void kernel_launch(void* const* d_in, const int* in_sizes, int n_in,
                              void* d_out, int out_size) {
    (void)in_sizes; (void)n_in; (void)out_size;
    const float* x      = (const float*)d_in[0];
    const float* vfirst = (const float*)d_in[1];
    const float* x_r = (const float*)d_in[2];
    const float* x_w = (const float*)d_in[3];
    const float* x_k = (const float*)d_in[4];
    const float* x_v = (const float*)d_in[5];
    const float* x_a = (const float*)d_in[6];
    const float* x_g = (const float*)d_in[7];
    const float* w0  = (const float*)d_in[8];
    const float* w1  = (const float*)d_in[9];
    const float* w2  = (const float*)d_in[10];
    const float* a0  = (const float*)d_in[11];
    const float* a1  = (const float*)d_in[12];
    const float* a2  = (const float*)d_in[13];
    const float* v0  = (const float*)d_in[14];
    const float* v1  = (const float*)d_in[15];
    const float* v2  = (const float*)d_in[16];
    const float* g1  = (const float*)d_in[17];
    const float* g2  = (const float*)d_in[18];
    const float* k_k = (const float*)d_in[19];
    const float* k_a = (const float*)d_in[20];
    const float* r_k = (const float*)d_in[21];
    const float* W_r = (const float*)d_in[22];
    const float* W_k = (const float*)d_in[23];
    const float* W_v = (const float*)d_in[24];
    const float* W_o = (const float*)d_in[25];
    const float* gnw = (const float*)d_in[26];
    const float* gnb = (const float*)d_in[27];
    float* out = (float*)d_out;

    float *p_xr, *p_xw, *p_xk, *p_xv, *p_xa, *p_xg;
    float *p_r, *p_k, *p_v, *p_w, *p_za, *p_zv, *p_g, *p_op;
    float *p_tw, *p_ta, *p_tv, *p_tg;
    cudaGetSymbolAddress((void**)&p_xr, g_xr);
    cudaGetSymbolAddress((void**)&p_xw, g_xw);
    cudaGetSymbolAddress((void**)&p_xk, g_xk);
    cudaGetSymbolAddress((void**)&p_xv, g_xv);
    cudaGetSymbolAddress((void**)&p_xa, g_xa);
    cudaGetSymbolAddress((void**)&p_xg, g_xg);
    cudaGetSymbolAddress((void**)&p_r,  g_r);
    cudaGetSymbolAddress((void**)&p_k,  g_k);
    cudaGetSymbolAddress((void**)&p_v,  g_v);
    cudaGetSymbolAddress((void**)&p_w,  g_w);
    cudaGetSymbolAddress((void**)&p_za, g_za);
    cudaGetSymbolAddress((void**)&p_zv, g_zv);
    cudaGetSymbolAddress((void**)&p_g,  g_g);
    cudaGetSymbolAddress((void**)&p_op, g_op);
    cudaGetSymbolAddress((void**)&p_tw, g_tw);
    cudaGetSymbolAddress((void**)&p_ta, g_ta);
    cudaGetSymbolAddress((void**)&p_tv, g_tv);
    cudaGetSymbolAddress((void**)&p_tg, g_tg);

    // 1) token shift + mixes
    mix_kernel<<<(BTn * Cn + 255) / 256, 256>>>(x, x_r, x_w, x_k, x_v, x_a, x_g);

    dim3 blk(256);
    dim3 grid_full(Cn / 128, BTn / 128);   // (16,16)
    dim3 grid_96(1, BTn / 128);
    dim3 grid_64(1, BTn / 128);
    dim3 grid_256(2, BTn / 128);

    // 2) projections
    sgemm_k<0><<<grid_full, blk>>>(p_xr, W_r, p_r, BTn, Cn, Cn);
    sgemm_k<0><<<grid_full, blk>>>(p_xk, W_k, p_k, BTn, Cn, Cn);
    sgemm_k<0><<<grid_full, blk>>>(p_xv, W_v, p_v, BTn, Cn, Cn);

    // 3) LoRA branches
    sgemm_k<1><<<grid_96,  blk>>>(p_xw, w1, p_tw, BTn, 96,  Cn);   // tanh
    sgemm_k<0><<<grid_full, blk>>>(p_tw, w2, p_w,  BTn, Cn,  96);
    sgemm_k<0><<<grid_96,  blk>>>(p_xa, a1, p_ta, BTn, 96,  Cn);
    sgemm_k<0><<<grid_full, blk>>>(p_ta, a2, p_za, BTn, Cn,  96);
    sgemm_k<0><<<grid_64,  blk>>>(p_xv, v1, p_tv, BTn, 64,  Cn);
    sgemm_k<0><<<grid_full, blk>>>(p_tv, v2, p_zv, BTn, Cn,  64);
    sgemm_k<2><<<grid_256, blk>>>(p_xg, g1, p_tg, BTn, 256, Cn);   // sigmoid
    sgemm_k<0><<<grid_full, blk>>>(p_tg, g2, p_g,  BTn, Cn, 256);

    // 4) per-head elementwise (decay, kk-normalize, k-mod, v-mix)
    ew2_kernel<<<BTn * Hn, 64>>>(w0, a0, v0, k_k, k_a, vfirst);

    // 5) WKV7 scan
    wkv7_scan<<<Bn * Hn, 256>>>();

    // 6) groupnorm + residual + gate
    gn_kernel<<<BTn * Hn, 64>>>(r_k, gnw, gnb);

    // 7) output projection
    sgemm_k<0><<<grid_full, blk>>>(p_op, W_o, out, BTn, Cn, Cn);
}

// round 2
// speedup vs baseline: 2.4873x; 2.4873x over previous
#include <cuda_runtime.h>
#include <math.h>

// Problem constants
#define Bn 2
#define Tn 1024
#define Cn 2048
#define Hn 32
#define Nn 64
#define BTn (Bn*Tn)

// ------------------------- scratch (static device globals) -------------------------
__device__ float g_xr[BTn*Cn];
__device__ float g_xw[BTn*Cn];
__device__ float g_xk[BTn*Cn];
__device__ float g_xv[BTn*Cn];
__device__ float g_xa[BTn*Cn];
__device__ float g_xg[BTn*Cn];
__device__ float g_r [BTn*Cn];
__device__ float g_k [BTn*Cn];
__device__ float g_v [BTn*Cn];
__device__ float g_w [BTn*Cn];   // holds w_lora output
__device__ float g_za[BTn*Cn];
__device__ float g_zv[BTn*Cn];
__device__ float g_g [BTn*Cn];
__device__ float g_y [BTn*Cn];
__device__ float g_op[BTn*Cn];
__device__ float g_tw[BTn*96];
__device__ float g_ta[BTn*96];
__device__ float g_tv[BTn*64];
__device__ float g_tg[BTn*256];
// packed scan operands: [B*H][T][6*64]  order: r,w,k,v,ah,bh
__device__ float g_pack[(size_t)Bn*Hn*Tn*384];

// ------------------------- tf32 helpers -------------------------
__device__ __forceinline__ unsigned f2tf32(float f) {
    unsigned u;
    asm("cvt.rna.tf32.f32 %0, %1;" : "=r"(u) : "f"(f));
    return u;
}

__device__ __forceinline__ void mma_tf32(float* d, const unsigned* a, const unsigned* b) {
    asm volatile(
        "mma.sync.aligned.m16n8k8.row.col.f32.tf32.tf32.f32 "
        "{%0,%1,%2,%3}, {%4,%5,%6,%7}, {%8,%9}, {%0,%1,%2,%3};"
        : "+f"(d[0]), "+f"(d[1]), "+f"(d[2]), "+f"(d[3])
        : "r"(a[0]), "r"(a[1]), "r"(a[2]), "r"(a[3]),
          "r"(b[0]), "r"(b[1]));
}

// ------------------------- tf32 tensor-core GEMM -------------------------
// C[M,N] = act(A[M,K] @ B[K,N]); row-major. Requires M%BM==0, N%BN==0, K%16==0.
// ACT: 0=none, 1=tanh, 2=sigmoid
template<int BM, int BN, int WM, int WN, int ACT>
__global__ void __launch_bounds__((BM/WM)*(BN/WN)*32)
mma_gemm(const float* __restrict__ A, const float* __restrict__ B,
         float* __restrict__ C, int M, int N, int K) {
    constexpr int KT = 16;
    constexpr int WARPS_M = BM / WM;
    constexpr int WARPS_N = BN / WN;
    constexpr int NTHREADS = WARPS_M * WARPS_N * 32;
    constexpr int MT = WM / 16;
    constexpr int NT = WN / 8;
    constexpr int AS = BM + 4;   // stride % 32 == 4 for conflict-free frag loads
    constexpr int BS = BN + 4;

    __shared__ unsigned Asm[KT][AS];
    __shared__ unsigned Bsm[KT][BS];

    const int tid = threadIdx.x;
    const int wid = tid >> 5, lane = tid & 31;
    const int gid = lane >> 2, tig = lane & 3;
    const int warp_m = wid / WARPS_N, warp_n = wid % WARPS_N;
    const int wm = warp_m * WM, wn = warp_n * WN;
    const int bm = blockIdx.y * BM, bn = blockIdx.x * BN;

    float acc[MT][NT][4];
#pragma unroll
    for (int i = 0; i < MT; i++)
#pragma unroll
        for (int j = 0; j < NT; j++)
#pragma unroll
            for (int q = 0; q < 4; q++) acc[i][j][q] = 0.f;

    for (int k0 = 0; k0 < K; k0 += KT) {
        // load A tile (row-major global -> k-major smem, tf32 converted)
#pragma unroll
        for (int i = 0; i < (BM * KT) / (4 * NTHREADS); i++) {
            int id = tid + i * NTHREADS;        // float4 id
            int m = id >> 2;                    // KT/16: 4 float4 per row
            int kq = (id & 3) * 4;
            float4 v = *(const float4*)(A + (size_t)(bm + m) * K + k0 + kq);
            Asm[kq + 0][m] = f2tf32(v.x);
            Asm[kq + 1][m] = f2tf32(v.y);
            Asm[kq + 2][m] = f2tf32(v.z);
            Asm[kq + 3][m] = f2tf32(v.w);
        }
        // load B tile (row-major copy)
#pragma unroll
        for (int i = 0; i < (BN * KT) / (4 * NTHREADS); i++) {
            int id = tid + i * NTHREADS;
            int kr = id / (BN / 4);
            int nq = (id % (BN / 4)) * 4;
            float4 v = *(const float4*)(B + (size_t)(k0 + kr) * N + bn + nq);
            Bsm[kr][nq + 0] = f2tf32(v.x);
            Bsm[kr][nq + 1] = f2tf32(v.y);
            Bsm[kr][nq + 2] = f2tf32(v.z);
            Bsm[kr][nq + 3] = f2tf32(v.w);
        }
        __syncthreads();

#pragma unroll
        for (int kk = 0; kk < KT; kk += 8) {
            unsigned af[MT][4], bf[NT][2];
#pragma unroll
            for (int mt = 0; mt < MT; mt++) {
                int rm = wm + mt * 16 + gid;
                af[mt][0] = Asm[kk + tig][rm];
                af[mt][1] = Asm[kk + tig][rm + 8];
                af[mt][2] = Asm[kk + tig + 4][rm];
                af[mt][3] = Asm[kk + tig + 4][rm + 8];
            }
#pragma unroll
            for (int nt = 0; nt < NT; nt++) {
                int cn = wn + nt * 8 + gid;
                bf[nt][0] = Bsm[kk + tig][cn];
                bf[nt][1] = Bsm[kk + tig + 4][cn];
            }
#pragma unroll
            for (int mt = 0; mt < MT; mt++)
#pragma unroll
                for (int nt = 0; nt < NT; nt++)
                    mma_tf32(acc[mt][nt], af[mt], bf[nt]);
        }
        __syncthreads();
    }

    // epilogue
#pragma unroll
    for (int mt = 0; mt < MT; mt++) {
#pragma unroll
        for (int nt = 0; nt < NT; nt++) {
            int r0 = bm + wm + mt * 16 + gid;
            int c = bn + wn + nt * 8 + tig * 2;
            float v0 = acc[mt][nt][0], v1 = acc[mt][nt][1];
            float v2 = acc[mt][nt][2], v3 = acc[mt][nt][3];
            if (ACT == 1) { v0 = tanhf(v0); v1 = tanhf(v1); v2 = tanhf(v2); v3 = tanhf(v3); }
            if (ACT == 2) {
                v0 = 1.f / (1.f + expf(-v0)); v1 = 1.f / (1.f + expf(-v1));
                v2 = 1.f / (1.f + expf(-v2)); v3 = 1.f / (1.f + expf(-v3));
            }
            *(float2*)(C + (size_t)r0 * N + c) = make_float2(v0, v1);
            *(float2*)(C + (size_t)(r0 + 8) * N + c) = make_float2(v2, v3);
        }
    }
}

// ------------------------- token shift + 6 mixes -------------------------
__global__ void mix_kernel(const float* __restrict__ x,
                           const float* __restrict__ cr, const float* __restrict__ cw,
                           const float* __restrict__ ck, const float* __restrict__ cv,
                           const float* __restrict__ ca, const float* __restrict__ cg) {
    size_t i = (size_t)blockIdx.x * blockDim.x + threadIdx.x;
    if (i >= (size_t)BTn * Cn) return;
    int c = (int)(i % Cn);
    size_t bt = i / Cn;
    int t = (int)(bt % Tn);
    float xc = x[i];
    float prev = (t == 0) ? 0.f : x[i - Cn];
    float dx = prev - xc;
    g_xr[i] = xc + dx * cr[c];
    g_xw[i] = xc + dx * cw[c];
    g_xk[i] = xc + dx * ck[c];
    g_xv[i] = xc + dx * cv[c];
    g_xa[i] = xc + dx * ca[c];
    g_xg[i] = xc + dx * cg[c];
}

// ------------------------- per-head elementwise stage 2 -------------------------
// decay, ICLR a, v-mix, k modification, normalized kk -> writes packed scan operands
__global__ void ew2_kernel(const float* __restrict__ w0, const float* __restrict__ a0,
                           const float* __restrict__ v0, const float* __restrict__ kkw,
                           const float* __restrict__ kaw, const float* __restrict__ vfirst) {
    int bt = blockIdx.x / Hn;
    int h  = blockIdx.x % Hn;
    int n  = threadIdx.x;          // 0..63
    int c  = h * Nn + n;
    size_t idx = (size_t)bt * Cn + c;
    int b = bt / Tn, t = bt % Tn;
    size_t pb = ((size_t)(b * Hn + h) * Tn + t) * 384;

    __shared__ float red[64];
    float kraw = g_k[idx];
    float kkp = kraw * kkw[c];
    red[n] = kkp * kkp;
    __syncthreads();
#pragma unroll
    for (int s = 32; s > 0; s >>= 1) { if (n < s) red[n] += red[n + s]; __syncthreads(); }
    float norm = sqrtf(red[0]);
    float kkn = kkp / fmaxf(norm, 1e-12f);

    float av = 1.f / (1.f + expf(-(a0[c] + g_za[idx])));
    float xw = -(w0[c] + g_w[idx]);
    float sp = (xw > 20.f) ? xw : log1pf(expf(xw));     // softplus(-(w0+w_lora))
    float wv = expf(-expf(-0.5f - sp));
    float vs = 1.f / (1.f + expf(-(v0[c] + g_zv[idx])));
    float vraw = g_v[idx];
    float vv = vraw + (vfirst[idx] - vraw) * vs;

    g_pack[pb +       n] = g_r[idx];
    g_pack[pb +  64 + n] = wv;
    g_pack[pb + 128 + n] = kraw * (1.f + (av - 1.f) * kaw[c]);
    g_pack[pb + 192 + n] = vv;
    g_pack[pb + 256 + n] = -kkn;
    g_pack[pb + 320 + n] = kkn * av;
}

// ------------------------- WKV7 sequential scan (prefetched, packed) -------------------------
// grid = B*H blocks; 256 threads; thread (v=tid>>2, kq=tid&3) owns S[v][16*kq..16*kq+15]
__global__ void __launch_bounds__(256) wkv7_scan() {
    int bh = blockIdx.x;
    int b = bh / Hn, h = bh % Hn;
    int tid = threadIdx.x;
    int v = tid >> 2;
    int kq = tid & 3;

    float S[16];
#pragma unroll
    for (int i = 0; i < 16; i++) S[i] = 0.f;

    __shared__ float sm[2][384];
    const float* pk = g_pack + (size_t)bh * Tn * 384;
    size_t ybase = (size_t)b * Tn * Cn + (size_t)h * Nn;

    // prologue: prefetch t=0
    float pre0 = pk[tid];
    float pre1 = (tid < 128) ? pk[256 + tid] : 0.f;

    int buf = 0;
    for (int t = 0; t < Tn; t++) {
        sm[buf][tid] = pre0;
        if (tid < 128) sm[buf][256 + tid] = pre1;
        __syncthreads();

        if (t + 1 < Tn) {
            const float* p = pk + (size_t)(t + 1) * 384;
            pre0 = p[tid];
            if (tid < 128) pre1 = p[256 + tid];
        }

        const float* r_  = sm[buf];
        const float* w_  = sm[buf] + 64;
        const float* k_  = sm[buf] + 128;
        const float* v_  = sm[buf] + 192;
        const float* ah_ = sm[buf] + 256;
        const float* bh_ = sm[buf] + 320;

        float sa = 0.f;
#pragma unroll
        for (int i = 0; i < 16; i++) sa = fmaf(S[i], ah_[kq * 16 + i], sa);
        sa += __shfl_xor_sync(0xffffffffu, sa, 1);
        sa += __shfl_xor_sync(0xffffffffu, sa, 2);

        float vv = v_[v];
        float y = 0.f;
#pragma unroll
        for (int i = 0; i < 16; i++) {
            int kk = kq * 16 + i;
            S[i] = fmaf(S[i], w_[kk], fmaf(sa, bh_[kk], vv * k_[kk]));
            y = fmaf(S[i], r_[kk], y);
        }
        y += __shfl_xor_sync(0xffffffffu, y, 1);
        y += __shfl_xor_sync(0xffffffffu, y, 2);
        if (kq == 0) g_y[ybase + (size_t)t * Cn + v] = y;
        buf ^= 1;
    }
}

// ------------------------- groupnorm + rk residual + gate -------------------------
__global__ void gn_kernel(const float* __restrict__ r_k, const float* __restrict__ gnw,
                          const float* __restrict__ gnb) {
    int bt = blockIdx.x / Hn;
    int h  = blockIdx.x % Hn;
    int n  = threadIdx.x;
    int c  = h * Nn + n;
    size_t idx = (size_t)bt * Cn + c;
    int b = bt / Tn, t = bt % Tn;
    size_t pb = ((size_t)(b * Hn + h) * Tn + t) * 384;

    __shared__ float red[64];
    float yv = g_y[idx];
    red[n] = yv;
    __syncthreads();
#pragma unroll
    for (int s = 32; s > 0; s >>= 1) { if (n < s) red[n] += red[n + s]; __syncthreads(); }
    float mu = red[0] * (1.f / 64.f);
    __syncthreads();

    float d = yv - mu;
    red[n] = d * d;
    __syncthreads();
#pragma unroll
    for (int s = 32; s > 0; s >>= 1) { if (n < s) red[n] += red[n + s]; __syncthreads(); }
    float var = red[0] * (1.f / 64.f);
    __syncthreads();

    float yn = d * rsqrtf(var + (float)(Nn * 1e-5)) * gnw[c] + gnb[c];

    float rr = g_pack[pb + n];
    float kk = g_pack[pb + 128 + n];
    float vv = g_pack[pb + 192 + n];
    float dp = rr * kk * r_k[c];
    red[n] = dp;
    __syncthreads();
#pragma unroll
    for (int s = 32; s > 0; s >>= 1) { if (n < s) red[n] += red[n + s]; __syncthreads(); }
    float dot = red[0];

    g_op[idx] = (yn + dot * vv) * g_g[idx];
}

// ------------------------- launch -------------------------
extern "C" void kernel_launch(void* const* d_in, const int* in_sizes, int n_in,
                              void* d_out, int out_size) {
    (void)in_sizes; (void)n_in; (void)out_size;
    const float* x      = (const float*)d_in[0];
    const float* vfirst = (const float*)d_in[1];
    const float* x_r = (const float*)d_in[2];
    const float* x_w = (const float*)d_in[3];
    const float* x_k = (const float*)d_in[4];
    const float* x_v = (const float*)d_in[5];
    const float* x_a = (const float*)d_in[6];
    const float* x_g = (const float*)d_in[7];
    const float* w0  = (const float*)d_in[8];
    const float* w1  = (const float*)d_in[9];
    const float* w2  = (const float*)d_in[10];
    const float* a0  = (const float*)d_in[11];
    const float* a1  = (const float*)d_in[12];
    const float* a2  = (const float*)d_in[13];
    const float* v0  = (const float*)d_in[14];
    const float* v1  = (const float*)d_in[15];
    const float* v2  = (const float*)d_in[16];
    const float* g1  = (const float*)d_in[17];
    const float* g2  = (const float*)d_in[18];
    const float* k_k = (const float*)d_in[19];
    const float* k_a = (const float*)d_in[20];
    const float* r_k = (const float*)d_in[21];
    const float* W_r = (const float*)d_in[22];
    const float* W_k = (const float*)d_in[23];
    const float* W_v = (const float*)d_in[24];
    const float* W_o = (const float*)d_in[25];
    const float* gnw = (const float*)d_in[26];
    const float* gnb = (const float*)d_in[27];
    float* out = (float*)d_out;

    float *p_xr, *p_xw, *p_xk, *p_xv, *p_xa, *p_xg;
    float *p_r, *p_k, *p_v, *p_w, *p_za, *p_zv, *p_g, *p_op;
    float *p_tw, *p_ta, *p_tv, *p_tg;
    cudaGetSymbolAddress((void**)&p_xr, g_xr);
    cudaGetSymbolAddress((void**)&p_xw, g_xw);
    cudaGetSymbolAddress((void**)&p_xk, g_xk);
    cudaGetSymbolAddress((void**)&p_xv, g_xv);
    cudaGetSymbolAddress((void**)&p_xa, g_xa);
    cudaGetSymbolAddress((void**)&p_xg, g_xg);
    cudaGetSymbolAddress((void**)&p_r,  g_r);
    cudaGetSymbolAddress((void**)&p_k,  g_k);
    cudaGetSymbolAddress((void**)&p_v,  g_v);
    cudaGetSymbolAddress((void**)&p_w,  g_w);
    cudaGetSymbolAddress((void**)&p_za, g_za);
    cudaGetSymbolAddress((void**)&p_zv, g_zv);
    cudaGetSymbolAddress((void**)&p_g,  g_g);
    cudaGetSymbolAddress((void**)&p_op, g_op);
    cudaGetSymbolAddress((void**)&p_tw, g_tw);
    cudaGetSymbolAddress((void**)&p_ta, g_ta);
    cudaGetSymbolAddress((void**)&p_tv, g_tv);
    cudaGetSymbolAddress((void**)&p_tg, g_tg);

    // 1) token shift + mixes
    mix_kernel<<<(BTn * Cn + 255) / 256, 256>>>(x, x_r, x_w, x_k, x_v, x_a, x_g);

    // cfgA: 128x128 tiles, 8 warps | cfgB: 64x32 tiles, 4 warps (skinny N)
    #define CFGA 128, 128, 64, 32
    #define CFGB 64, 32, 32, 16
    dim3 blkA(256), blkB(128);

    // 2) projections (N=2048, K=2048)
    mma_gemm<CFGA, 0><<<dim3(16, 16), blkA>>>(p_xr, W_r, p_r, BTn, Cn, Cn);
    mma_gemm<CFGA, 0><<<dim3(16, 16), blkA>>>(p_xk, W_k, p_k, BTn, Cn, Cn);
    mma_gemm<CFGA, 0><<<dim3(16, 16), blkA>>>(p_xv, W_v, p_v, BTn, Cn, Cn);

    // 3) LoRA branches: up (skinny N) with cfgB, down (N=2048, small K) with cfgA
    mma_gemm<CFGB, 1><<<dim3(96 / 32, BTn / 64), blkB>>>(p_xw, w1, p_tw, BTn, 96, Cn);   // tanh
    mma_gemm<CFGA, 0><<<dim3(16, 16), blkA>>>(p_tw, w2, p_w, BTn, Cn, 96);
    mma_gemm<CFGB, 0><<<dim3(96 / 32, BTn / 64), blkB>>>(p_xa, a1, p_ta, BTn, 96, Cn);
    mma_gemm<CFGA, 0><<<dim3(16, 16), blkA>>>(p_ta, a2, p_za, BTn, Cn, 96);
    mma_gemm<CFGB, 0><<<dim3(64 / 32, BTn / 64), blkB>>>(p_xv, v1, p_tv, BTn, 64, Cn);
    mma_gemm<CFGA, 0><<<dim3(16, 16), blkA>>>(p_tv, v2, p_zv, BTn, Cn, 64);
    mma_gemm<CFGB, 2><<<dim3(256 / 32, BTn / 64), blkB>>>(p_xg, g1, p_tg, BTn, 256, Cn); // sigmoid
    mma_gemm<CFGA, 0><<<dim3(16, 16), blkA>>>(p_tg, g2, p_g, BTn, Cn, 256);

    // 4) per-head elementwise (decay, kk-normalize, k-mod, v-mix) -> packed
    ew2_kernel<<<BTn * Hn, 64>>>(w0, a0, v0, k_k, k_a, vfirst);

    // 5) WKV7 scan
    wkv7_scan<<<Bn * Hn, 256>>>();

    // 6) groupnorm + residual + gate
    gn_kernel<<<BTn * Hn, 64>>>(r_k, gnw, gnb);

    // 7) output projection
    mma_gemm<CFGA, 0><<<dim3(16, 16), blkA>>>(p_op, W_o, out, BTn, Cn, Cn);
}

// round 3
// speedup vs baseline: 3.3152x; 1.3329x over previous
#include <cuda_runtime.h>
#include <math.h>

// Problem constants
#define Bn 2
#define Tn 1024
#define Cn 2048
#define Hn 32
#define Nn 64
#define BTn (Bn*Tn)

// ------------------------- scratch (static device globals) -------------------------
__device__ float g_xr[BTn*Cn];
__device__ float g_xw[BTn*Cn];
__device__ float g_xk[BTn*Cn];
__device__ float g_xv[BTn*Cn];
__device__ float g_xa[BTn*Cn];
__device__ float g_xg[BTn*Cn];
__device__ float g_r [BTn*Cn];
__device__ float g_k [BTn*Cn];
__device__ float g_v [BTn*Cn];
__device__ float g_w [BTn*Cn];
__device__ float g_za[BTn*Cn];
__device__ float g_zv[BTn*Cn];
__device__ float g_g [BTn*Cn];
__device__ float g_y [BTn*Cn];
__device__ float g_op[BTn*Cn];
__device__ float g_tw[BTn*96];
__device__ float g_ta[BTn*96];
__device__ float g_tv[BTn*64];
__device__ float g_tg[BTn*256];
// packed scan operands: [B*H][T][6*64]  order: r,w,k,v,ah,bh
__device__ float g_pack[(size_t)Bn*Hn*Tn*384];

// ------------------------- helpers -------------------------
__device__ __forceinline__ unsigned f2tf32(float f) {
    unsigned u;
    asm("cvt.rna.tf32.f32 %0, %1;" : "=r"(u) : "f"(f));
    return u;
}

__device__ __forceinline__ void mma_tf32(float* d, const unsigned* a, const unsigned* b) {
    asm volatile(
        "mma.sync.aligned.m16n8k8.row.col.f32.tf32.tf32.f32 "
        "{%0,%1,%2,%3}, {%4,%5,%6,%7}, {%8,%9}, {%0,%1,%2,%3};"
        : "+f"(d[0]), "+f"(d[1]), "+f"(d[2]), "+f"(d[3])
        : "r"(a[0]), "r"(a[1]), "r"(a[2]), "r"(a[3]),
          "r"(b[0]), "r"(b[1]));
}

__device__ __forceinline__ void cp16(void* smem, const void* g) {
    unsigned saddr = (unsigned)__cvta_generic_to_shared(smem);
    asm volatile("cp.async.cg.shared.global [%0], [%1], 16;" :: "r"(saddr), "l"(g));
}
__device__ __forceinline__ void cp_commit() { asm volatile("cp.async.commit_group;"); }
__device__ __forceinline__ void cp_wait1()  { asm volatile("cp.async.wait_group 1;"); }

// ------------------------- batched, pipelined tf32 GEMM -------------------------
// For each z: C[z] = act(A[z][M,K] @ B[z][K,N]); row-major; M%BM==0, N%32==0, K%16==0.
struct GB {
    const float* A[4];
    const float* Bw[4];
    float*       C[4];
    int N[4];
    int K[4];
    int act[4];   // 0=none 1=tanh 2=sigmoid
};

template<int BM, int BN, int WM, int WN>
__global__ void __launch_bounds__((BM/WM)*(BN/WN)*32)
gemm_pipe(GB p) {
    constexpr int KT = 16;
    constexpr int WARPS_M = BM / WM;
    constexpr int WARPS_N = BN / WN;
    constexpr int NTHREADS = WARPS_M * WARPS_N * 32;
    constexpr int MT = WM / 16;
    constexpr int NT_ = WN / 8;
    constexpr int ASTR = KT + 4;   // A smem row stride (floats), layout [m][k]
    constexpr int BSTR = BN + 8;   // B smem row stride (floats), layout [k][n]

    __shared__ float Asm[2][BM][ASTR];
    __shared__ float Bsm[2][KT][BSTR];

    const int z = blockIdx.z;
    const float* A = p.A[z];
    const float* B = p.Bw[z];
    float* C = p.C[z];
    const int N = p.N[z], K = p.K[z], act = p.act[z];
    const int bn = blockIdx.x * BN;
    if (bn >= N) return;
    const int bm = blockIdx.y * BM;

    const int tid = threadIdx.x;
    const int wid = tid >> 5, lane = tid & 31;
    const int gid = lane >> 2, tig = lane & 3;
    const int warp_m = wid / WARPS_N, warp_n = wid % WARPS_N;
    const int wm = warp_m * WM, wn = warp_n * WN;

    float acc[MT][NT_][4];
#pragma unroll
    for (int i = 0; i < MT; i++)
#pragma unroll
        for (int j = 0; j < NT_; j++)
#pragma unroll
            for (int q = 0; q < 4; q++) acc[i][j][q] = 0.f;

    auto load_stage = [&](int s, int k0) {
#pragma unroll
        for (int i = 0; i < (BM * 4) / NTHREADS; i++) {
            int id = tid + i * NTHREADS;
            int m = id >> 2, kc = (id & 3) * 4;
            cp16(&Asm[s][m][kc], A + (size_t)(bm + m) * K + k0 + kc);
        }
#pragma unroll
        for (int i = 0; i < (KT * BN / 4) / NTHREADS; i++) {
            int id = tid + i * NTHREADS;
            int kr = id / (BN / 4), nq = (id % (BN / 4)) * 4;
            cp16(&Bsm[s][kr][nq], B + (size_t)(k0 + kr) * N + bn + nq);
        }
    };

    const int nk = K / KT;
    load_stage(0, 0);
    cp_commit();

    for (int kt = 0; kt < nk; kt++) {
        __syncthreads();   // all threads done reading stage (kt+1)&1 (from iter kt-1)
        if (kt + 1 < nk) load_stage((kt + 1) & 1, (kt + 1) * KT);
        cp_commit();
        cp_wait1();        // stage kt&1 data arrived
        __syncthreads();

        const int s = kt & 1;
#pragma unroll
        for (int kk = 0; kk < KT; kk += 8) {
            unsigned af[MT][4], bf[NT_][2];
#pragma unroll
            for (int mt = 0; mt < MT; mt++) {
                int rm = wm + mt * 16 + gid;
                af[mt][0] = f2tf32(Asm[s][rm][kk + tig]);
                af[mt][1] = f2tf32(Asm[s][rm + 8][kk + tig]);
                af[mt][2] = f2tf32(Asm[s][rm][kk + tig + 4]);
                af[mt][3] = f2tf32(Asm[s][rm + 8][kk + tig + 4]);
            }
#pragma unroll
            for (int nt = 0; nt < NT_; nt++) {
                int cn = wn + nt * 8 + gid;
                bf[nt][0] = f2tf32(Bsm[s][kk + tig][cn]);
                bf[nt][1] = f2tf32(Bsm[s][kk + tig + 4][cn]);
            }
#pragma unroll
            for (int mt = 0; mt < MT; mt++)
#pragma unroll
                for (int nt = 0; nt < NT_; nt++)
                    mma_tf32(acc[mt][nt], af[mt], bf[nt]);
        }
    }

    // epilogue
#pragma unroll
    for (int mt = 0; mt < MT; mt++) {
#pragma unroll
        for (int nt = 0; nt < NT_; nt++) {
            int r0 = bm + wm + mt * 16 + gid;
            int c = bn + wn + nt * 8 + tig * 2;
            float v0 = acc[mt][nt][0], v1 = acc[mt][nt][1];
            float v2 = acc[mt][nt][2], v3 = acc[mt][nt][3];
            if (act == 1) {
                v0 = tanhf(v0); v1 = tanhf(v1); v2 = tanhf(v2); v3 = tanhf(v3);
            } else if (act == 2) {
                v0 = 1.f / (1.f + expf(-v0)); v1 = 1.f / (1.f + expf(-v1));
                v2 = 1.f / (1.f + expf(-v2)); v3 = 1.f / (1.f + expf(-v3));
            }
            *(float2*)(C + (size_t)r0 * N + c) = make_float2(v0, v1);
            *(float2*)(C + (size_t)(r0 + 8) * N + c) = make_float2(v2, v3);
        }
    }
}

// ------------------------- token shift + 6 mixes -------------------------
__global__ void mix_kernel(const float* __restrict__ x,
                           const float* __restrict__ cr, const float* __restrict__ cw,
                           const float* __restrict__ ck, const float* __restrict__ cv,
                           const float* __restrict__ ca, const float* __restrict__ cg) {
    size_t i = (size_t)blockIdx.x * blockDim.x + threadIdx.x;
    if (i >= (size_t)BTn * Cn) return;
    int c = (int)(i % Cn);
    size_t bt = i / Cn;
    int t = (int)(bt % Tn);
    float xc = x[i];
    float prev = (t == 0) ? 0.f : x[i - Cn];
    float dx = prev - xc;
    g_xr[i] = xc + dx * cr[c];
    g_xw[i] = xc + dx * cw[c];
    g_xk[i] = xc + dx * ck[c];
    g_xv[i] = xc + dx * cv[c];
    g_xa[i] = xc + dx * ca[c];
    g_xg[i] = xc + dx * cg[c];
}

// ------------------------- per-head elementwise stage 2 -------------------------
__global__ void ew2_kernel(const float* __restrict__ w0, const float* __restrict__ a0,
                           const float* __restrict__ v0, const float* __restrict__ kkw,
                           const float* __restrict__ kaw, const float* __restrict__ vfirst) {
    int bt = blockIdx.x / Hn;
    int h  = blockIdx.x % Hn;
    int n  = threadIdx.x;          // 0..63
    int c  = h * Nn + n;
    size_t idx = (size_t)bt * Cn + c;
    int b = bt / Tn, t = bt % Tn;
    size_t pb = ((size_t)(b * Hn + h) * Tn + t) * 384;

    __shared__ float red[64];
    float kraw = g_k[idx];
    float kkp = kraw * kkw[c];
    red[n] = kkp * kkp;
    __syncthreads();
#pragma unroll
    for (int s = 32; s > 0; s >>= 1) { if (n < s) red[n] += red[n + s]; __syncthreads(); }
    float norm = sqrtf(red[0]);
    float kkn = kkp / fmaxf(norm, 1e-12f);

    float av = 1.f / (1.f + expf(-(a0[c] + g_za[idx])));
    float xw = -(w0[c] + g_w[idx]);
    float sp = (xw > 20.f) ? xw : log1pf(expf(xw));
    float wv = expf(-expf(-0.5f - sp));
    float vs = 1.f / (1.f + expf(-(v0[c] + g_zv[idx])));
    float vraw = g_v[idx];
    float vv = vraw + (vfirst[idx] - vraw) * vs;

    g_pack[pb +       n] = g_r[idx];
    g_pack[pb +  64 + n] = wv;
    g_pack[pb + 128 + n] = kraw * (1.f + (av - 1.f) * kaw[c]);
    g_pack[pb + 192 + n] = vv;
    g_pack[pb + 256 + n] = -kkn;
    g_pack[pb + 320 + n] = kkn * av;
}

// ------------------------- WKV7 sequential scan -------------------------
__global__ void __launch_bounds__(256) wkv7_scan() {
    int bh = blockIdx.x;
    int b = bh / Hn, h = bh % Hn;
    int tid = threadIdx.x;
    int v = tid >> 2;
    int kq = tid & 3;

    float S[16];
#pragma unroll
    for (int i = 0; i < 16; i++) S[i] = 0.f;

    __shared__ float sm[2][384];
    const float* pk = g_pack + (size_t)bh * Tn * 384;
    size_t ybase = (size_t)b * Tn * Cn + (size_t)h * Nn;

    float pre0 = pk[tid];
    float pre1 = (tid < 128) ? pk[256 + tid] : 0.f;

    int buf = 0;
    for (int t = 0; t < Tn; t++) {
        sm[buf][tid] = pre0;
        if (tid < 128) sm[buf][256 + tid] = pre1;
        __syncthreads();

        if (t + 1 < Tn) {
            const float* p = pk + (size_t)(t + 1) * 384;
            pre0 = p[tid];
            if (tid < 128) pre1 = p[256 + tid];
        }

        const float* r_  = sm[buf];
        const float* w_  = sm[buf] + 64;
        const float* k_  = sm[buf] + 128;
        const float* v_  = sm[buf] + 192;
        const float* ah_ = sm[buf] + 256;
        const float* bh_ = sm[buf] + 320;
        const int kb = kq * 16;

        float sa0 = 0.f, sa1 = 0.f, sa2 = 0.f, sa3 = 0.f;
#pragma unroll
        for (int i = 0; i < 4; i++) {
            sa0 = fmaf(S[i],      ah_[kb + i],      sa0);
            sa1 = fmaf(S[4 + i],  ah_[kb + 4 + i],  sa1);
            sa2 = fmaf(S[8 + i],  ah_[kb + 8 + i],  sa2);
            sa3 = fmaf(S[12 + i], ah_[kb + 12 + i], sa3);
        }
        float sa = (sa0 + sa1) + (sa2 + sa3);
        sa += __shfl_xor_sync(0xffffffffu, sa, 1);
        sa += __shfl_xor_sync(0xffffffffu, sa, 2);

        float vv = v_[v];
        float y0 = 0.f, y1 = 0.f, y2 = 0.f, y3 = 0.f;
#pragma unroll
        for (int i = 0; i < 4; i++) {
            int k0 = kb + i, k1 = kb + 4 + i, k2 = kb + 8 + i, k3 = kb + 12 + i;
            S[i]      = fmaf(S[i],      w_[k0], fmaf(sa, bh_[k0], vv * k_[k0]));
            S[4 + i]  = fmaf(S[4 + i],  w_[k1], fmaf(sa, bh_[k1], vv * k_[k1]));
            S[8 + i]  = fmaf(S[8 + i],  w_[k2], fmaf(sa, bh_[k2], vv * k_[k2]));
            S[12 + i] = fmaf(S[12 + i], w_[k3], fmaf(sa, bh_[k3], vv * k_[k3]));
            y0 = fmaf(S[i],      r_[k0], y0);
            y1 = fmaf(S[4 + i],  r_[k1], y1);
            y2 = fmaf(S[8 + i],  r_[k2], y2);
            y3 = fmaf(S[12 + i], r_[k3], y3);
        }
        float y = (y0 + y1) + (y2 + y3);
        y += __shfl_xor_sync(0xffffffffu, y, 1);
        y += __shfl_xor_sync(0xffffffffu, y, 2);
        if (kq == 0) g_y[ybase + (size_t)t * Cn + v] = y;
        buf ^= 1;
    }
}

// ------------------------- groupnorm + rk residual + gate -------------------------
__global__ void gn_kernel(const float* __restrict__ r_k, const float* __restrict__ gnw,
                          const float* __restrict__ gnb) {
    int bt = blockIdx.x / Hn;
    int h  = blockIdx.x % Hn;
    int n  = threadIdx.x;
    int c  = h * Nn + n;
    size_t idx = (size_t)bt * Cn + c;
    int b = bt / Tn, t = bt % Tn;
    size_t pb = ((size_t)(b * Hn + h) * Tn + t) * 384;

    __shared__ float red[64];
    float yv = g_y[idx];
    red[n] = yv;
    __syncthreads();
#pragma unroll
    for (int s = 32; s > 0; s >>= 1) { if (n < s) red[n] += red[n + s]; __syncthreads(); }
    float mu = red[0] * (1.f / 64.f);
    __syncthreads();

    float d = yv - mu;
    red[n] = d * d;
    __syncthreads();
#pragma unroll
    for (int s = 32; s > 0; s >>= 1) { if (n < s) red[n] += red[n + s]; __syncthreads(); }
    float var = red[0] * (1.f / 64.f);
    __syncthreads();

    float yn = d * rsqrtf(var + (float)(Nn * 1e-5)) * gnw[c] + gnb[c];

    float rr = g_pack[pb + n];
    float kk = g_pack[pb + 128 + n];
    float vv = g_pack[pb + 192 + n];
    float dp = rr * kk * r_k[c];
    red[n] = dp;
    __syncthreads();
#pragma unroll
    for (int s = 32; s > 0; s >>= 1) { if (n < s) red[n] += red[n + s]; __syncthreads(); }
    float dot = red[0];

    g_op[idx] = (yn + dot * vv) * g_g[idx];
}

// ------------------------- launch -------------------------
extern "C" void kernel_launch(void* const* d_in, const int* in_sizes, int n_in,
                              void* d_out, int out_size) {
    (void)in_sizes; (void)n_in; (void)out_size;
    const float* x      = (const float*)d_in[0];
    const float* vfirst = (const float*)d_in[1];
    const float* x_r = (const float*)d_in[2];
    const float* x_w = (const float*)d_in[3];
    const float* x_k = (const float*)d_in[4];
    const float* x_v = (const float*)d_in[5];
    const float* x_a = (const float*)d_in[6];
    const float* x_g = (const float*)d_in[7];
    const float* w0  = (const float*)d_in[8];
    const float* w1  = (const float*)d_in[9];
    const float* w2  = (const float*)d_in[10];
    const float* a0  = (const float*)d_in[11];
    const float* a1  = (const float*)d_in[12];
    const float* a2  = (const float*)d_in[13];
    const float* v0  = (const float*)d_in[14];
    const float* v1  = (const float*)d_in[15];
    const float* v2  = (const float*)d_in[16];
    const float* g1  = (const float*)d_in[17];
    const float* g2  = (const float*)d_in[18];
    const float* k_k = (const float*)d_in[19];
    const float* k_a = (const float*)d_in[20];
    const float* r_k = (const float*)d_in[21];
    const float* W_r = (const float*)d_in[22];
    const float* W_k = (const float*)d_in[23];
    const float* W_v = (const float*)d_in[24];
    const float* W_o = (const float*)d_in[25];
    const float* gnw = (const float*)d_in[26];
    const float* gnb = (const float*)d_in[27];
    float* out = (float*)d_out;

    float *p_xr, *p_xw, *p_xk, *p_xv, *p_xa, *p_xg;
    float *p_r, *p_k, *p_v, *p_w, *p_za, *p_zv, *p_g, *p_op;
    float *p_tw, *p_ta, *p_tv, *p_tg;
    cudaGetSymbolAddress((void**)&p_xr, g_xr);
    cudaGetSymbolAddress((void**)&p_xw, g_xw);
    cudaGetSymbolAddress((void**)&p_xk, g_xk);
    cudaGetSymbolAddress((void**)&p_xv, g_xv);
    cudaGetSymbolAddress((void**)&p_xa, g_xa);
    cudaGetSymbolAddress((void**)&p_xg, g_xg);
    cudaGetSymbolAddress((void**)&p_r,  g_r);
    cudaGetSymbolAddress((void**)&p_k,  g_k);
    cudaGetSymbolAddress((void**)&p_v,  g_v);
    cudaGetSymbolAddress((void**)&p_w,  g_w);
    cudaGetSymbolAddress((void**)&p_za, g_za);
    cudaGetSymbolAddress((void**)&p_zv, g_zv);
    cudaGetSymbolAddress((void**)&p_g,  g_g);
    cudaGetSymbolAddress((void**)&p_op, g_op);
    cudaGetSymbolAddress((void**)&p_tw, g_tw);
    cudaGetSymbolAddress((void**)&p_ta, g_ta);
    cudaGetSymbolAddress((void**)&p_tv, g_tv);
    cudaGetSymbolAddress((void**)&p_tg, g_tg);

    // 1) token shift + mixes
    mix_kernel<<<(BTn * Cn + 255) / 256, 256>>>(x, x_r, x_w, x_k, x_v, x_a, x_g);

    // 2) r/k/v projections (batched over z)
    {
        GB p = {};
        p.A[0] = p_xr; p.A[1] = p_xk; p.A[2] = p_xv;
        p.Bw[0] = W_r; p.Bw[1] = W_k; p.Bw[2] = W_v;
        p.C[0] = p_r;  p.C[1] = p_k;  p.C[2] = p_v;
        for (int z = 0; z < 3; z++) { p.N[z] = Cn; p.K[z] = Cn; p.act[z] = 0; }
        gemm_pipe<128, 128, 64, 32><<<dim3(16, 16, 3), 256>>>(p);
    }

    // 3a) LoRA ups (skinny N, batched)
    {
        GB p = {};
        p.A[0] = p_xw; p.A[1] = p_xa; p.A[2] = p_xv; p.A[3] = p_xg;
        p.Bw[0] = w1;  p.Bw[1] = a1;  p.Bw[2] = v1;  p.Bw[3] = g1;
        p.C[0] = p_tw; p.C[1] = p_ta; p.C[2] = p_tv; p.C[3] = p_tg;
        p.N[0] = 96; p.N[1] = 96; p.N[2] = 64; p.N[3] = 256;
        for (int z = 0; z < 4; z++) p.K[z] = Cn;
        p.act[0] = 1; p.act[1] = 0; p.act[2] = 0; p.act[3] = 2;
        gemm_pipe<64, 32, 32, 16><<<dim3(8, BTn / 64, 4), 128>>>(p);
    }

    // 3b) LoRA downs (N=2048, small K, batched)
    {
        GB p = {};
        p.A[0] = p_tw; p.A[1] = p_ta; p.A[2] = p_tv; p.A[3] = p_tg;
        p.Bw[0] = w2;  p.Bw[1] = a2;  p.Bw[2] = v2;  p.Bw[3] = g2;
        p.C[0] = p_w;  p.C[1] = p_za; p.C[2] = p_zv; p.C[3] = p_g;
        p.K[0] = 96; p.K[1] = 96; p.K[2] = 64; p.K[3] = 256;
        for (int z = 0; z < 4; z++) { p.N[z] = Cn; p.act[z] = 0; }
        gemm_pipe<128, 128, 64, 32><<<dim3(16, 16, 4), 256>>>(p);
    }

    // 4) per-head elementwise -> packed scan operands
    ew2_kernel<<<BTn * Hn, 64>>>(w0, a0, v0, k_k, k_a, vfirst);

    // 5) WKV7 scan
    wkv7_scan<<<Bn * Hn, 256>>>();

    // 6) groupnorm + residual + gate
    gn_kernel<<<BTn * Hn, 64>>>(r_k, gnw, gnb);

    // 7) output projection
    {
        GB p = {};
        p.A[0] = p_op; p.Bw[0] = W_o; p.C[0] = out;
        p.N[0] = Cn; p.K[0] = Cn; p.act[0] = 0;
        gemm_pipe<128, 128, 64, 32><<<dim3(16, 16, 1), 256>>>(p);
    }
}

// round 4
// speedup vs baseline: 3.8565x; 1.1633x over previous
#include <cuda_runtime.h>
#include <math.h>

// Problem constants
#define Bn 2
#define Tn 1024
#define Cn 2048
#define Hn 32
#define Nn 64
#define BTn (Bn*Tn)

// ------------------------- scratch (static device globals) -------------------------
__device__ float g_xr[BTn*Cn];
__device__ float g_xw[BTn*Cn];
__device__ float g_xk[BTn*Cn];
__device__ float g_xv[BTn*Cn];
__device__ float g_xa[BTn*Cn];
__device__ float g_xg[BTn*Cn];
__device__ float g_r [BTn*Cn];
__device__ float g_k [BTn*Cn];
__device__ float g_v [BTn*Cn];
__device__ float g_w [BTn*Cn];
__device__ float g_za[BTn*Cn];
__device__ float g_zv[BTn*Cn];
__device__ float g_g [BTn*Cn];
__device__ float g_y [BTn*Cn];
__device__ float g_op[BTn*Cn];
__device__ float g_tw[BTn*96];
__device__ float g_ta[BTn*96];
__device__ float g_tv[BTn*64];
__device__ float g_tg[BTn*256];
// packed scan operands: [B*H][T][6*64]  order: r,w,k,v,ah,bh
__device__ float g_pack[(size_t)Bn*Hn*Tn*384];

// ------------------------- helpers -------------------------
__device__ __forceinline__ unsigned f2tf32(float f) {
    unsigned u;
    asm("cvt.rna.tf32.f32 %0, %1;" : "=r"(u) : "f"(f));
    return u;
}

__device__ __forceinline__ void mma_tf32(float* d, const unsigned* a, const unsigned* b) {
    asm volatile(
        "mma.sync.aligned.m16n8k8.row.col.f32.tf32.tf32.f32 "
        "{%0,%1,%2,%3}, {%4,%5,%6,%7}, {%8,%9}, {%0,%1,%2,%3};"
        : "+f"(d[0]), "+f"(d[1]), "+f"(d[2]), "+f"(d[3])
        : "r"(a[0]), "r"(a[1]), "r"(a[2]), "r"(a[3]),
          "r"(b[0]), "r"(b[1]));
}

__device__ __forceinline__ void cp16(void* smem, const void* g) {
    unsigned saddr = (unsigned)__cvta_generic_to_shared(smem);
    asm volatile("cp.async.cg.shared.global [%0], [%1], 16;" :: "r"(saddr), "l"(g));
}
__device__ __forceinline__ void cp_commit() { asm volatile("cp.async.commit_group;"); }
__device__ __forceinline__ void cp_wait1()  { asm volatile("cp.async.wait_group 1;"); }

// ------------------------- batched, pipelined tf32 GEMM -------------------------
struct GB {
    const float* A[4];
    const float* Bw[4];
    float*       C[4];
    int N[4];
    int K[4];
    int act[4];   // 0=none 1=tanh 2=sigmoid
};

template<int BM, int BN, int WM, int WN>
__global__ void __launch_bounds__((BM/WM)*(BN/WN)*32)
gemm_pipe(GB p) {
    constexpr int KT = 16;
    constexpr int WARPS_M = BM / WM;
    constexpr int WARPS_N = BN / WN;
    constexpr int NTHREADS = WARPS_M * WARPS_N * 32;
    constexpr int MT = WM / 16;
    constexpr int NT_ = WN / 8;
    constexpr int ASTR = KT + 4;
    constexpr int BSTR = BN + 8;

    __shared__ float Asm[2][BM][ASTR];
    __shared__ float Bsm[2][KT][BSTR];

    const int z = blockIdx.z;
    const float* A = p.A[z];
    const float* B = p.Bw[z];
    float* C = p.C[z];
    const int N = p.N[z], K = p.K[z], act = p.act[z];
    const int bn = blockIdx.x * BN;
    if (bn >= N) return;
    const int bm = blockIdx.y * BM;

    const int tid = threadIdx.x;
    const int wid = tid >> 5, lane = tid & 31;
    const int gid = lane >> 2, tig = lane & 3;
    const int warp_m = wid / WARPS_N, warp_n = wid % WARPS_N;
    const int wm = warp_m * WM, wn = warp_n * WN;

    float acc[MT][NT_][4];
#pragma unroll
    for (int i = 0; i < MT; i++)
#pragma unroll
        for (int j = 0; j < NT_; j++)
#pragma unroll
            for (int q = 0; q < 4; q++) acc[i][j][q] = 0.f;

    auto load_stage = [&](int s, int k0) {
#pragma unroll
        for (int i = 0; i < (BM * 4) / NTHREADS; i++) {
            int id = tid + i * NTHREADS;
            int m = id >> 2, kc = (id & 3) * 4;
            cp16(&Asm[s][m][kc], A + (size_t)(bm + m) * K + k0 + kc);
        }
#pragma unroll
        for (int i = 0; i < (KT * BN / 4) / NTHREADS; i++) {
            int id = tid + i * NTHREADS;
            int kr = id / (BN / 4), nq = (id % (BN / 4)) * 4;
            cp16(&Bsm[s][kr][nq], B + (size_t)(k0 + kr) * N + bn + nq);
        }
    };

    const int nk = K / KT;
    load_stage(0, 0);
    cp_commit();

    for (int kt = 0; kt < nk; kt++) {
        __syncthreads();
        if (kt + 1 < nk) load_stage((kt + 1) & 1, (kt + 1) * KT);
        cp_commit();
        cp_wait1();
        __syncthreads();

        const int s = kt & 1;
#pragma unroll
        for (int kk = 0; kk < KT; kk += 8) {
            unsigned af[MT][4], bf[NT_][2];
#pragma unroll
            for (int mt = 0; mt < MT; mt++) {
                int rm = wm + mt * 16 + gid;
                af[mt][0] = f2tf32(Asm[s][rm][kk + tig]);
                af[mt][1] = f2tf32(Asm[s][rm + 8][kk + tig]);
                af[mt][2] = f2tf32(Asm[s][rm][kk + tig + 4]);
                af[mt][3] = f2tf32(Asm[s][rm + 8][kk + tig + 4]);
            }
#pragma unroll
            for (int nt = 0; nt < NT_; nt++) {
                int cn = wn + nt * 8 + gid;
                bf[nt][0] = f2tf32(Bsm[s][kk + tig][cn]);
                bf[nt][1] = f2tf32(Bsm[s][kk + tig + 4][cn]);
            }
#pragma unroll
            for (int mt = 0; mt < MT; mt++)
#pragma unroll
                for (int nt = 0; nt < NT_; nt++)
                    mma_tf32(acc[mt][nt], af[mt], bf[nt]);
        }
    }

#pragma unroll
    for (int mt = 0; mt < MT; mt++) {
#pragma unroll
        for (int nt = 0; nt < NT_; nt++) {
            int r0 = bm + wm + mt * 16 + gid;
            int c = bn + wn + nt * 8 + tig * 2;
            float v0 = acc[mt][nt][0], v1 = acc[mt][nt][1];
            float v2 = acc[mt][nt][2], v3 = acc[mt][nt][3];
            if (act == 1) {
                v0 = tanhf(v0); v1 = tanhf(v1); v2 = tanhf(v2); v3 = tanhf(v3);
            } else if (act == 2) {
                v0 = 1.f / (1.f + expf(-v0)); v1 = 1.f / (1.f + expf(-v1));
                v2 = 1.f / (1.f + expf(-v2)); v3 = 1.f / (1.f + expf(-v3));
            }
            *(float2*)(C + (size_t)r0 * N + c) = make_float2(v0, v1);
            *(float2*)(C + (size_t)(r0 + 8) * N + c) = make_float2(v2, v3);
        }
    }
}

// ------------------------- token shift + 6 mixes (float4) -------------------------
__global__ void mix_kernel(const float4* __restrict__ x,
                           const float4* __restrict__ cr, const float4* __restrict__ cw,
                           const float4* __restrict__ ck, const float4* __restrict__ cv,
                           const float4* __restrict__ ca, const float4* __restrict__ cg) {
    size_t i = (size_t)blockIdx.x * blockDim.x + threadIdx.x;
    constexpr size_t TOT = (size_t)BTn * Cn / 4;
    constexpr int C4 = Cn / 4;
    if (i >= TOT) return;
    int c = (int)(i % C4);
    size_t bt = i / C4;
    int t = (int)(bt % Tn);
    float4 xc = x[i];
    float4 prev = (t == 0) ? make_float4(0.f, 0.f, 0.f, 0.f) : x[i - C4];
    float4 dx = make_float4(prev.x - xc.x, prev.y - xc.y, prev.z - xc.z, prev.w - xc.w);
#define MIXO(dst, coef) { \
    float4 cc = coef[c]; \
    ((float4*)dst)[i] = make_float4(fmaf(dx.x, cc.x, xc.x), fmaf(dx.y, cc.y, xc.y), \
                                    fmaf(dx.z, cc.z, xc.z), fmaf(dx.w, cc.w, xc.w)); }
    MIXO(g_xr, cr); MIXO(g_xw, cw); MIXO(g_xk, ck);
    MIXO(g_xv, cv); MIXO(g_xa, ca); MIXO(g_xg, cg);
#undef MIXO
}

// ------------------------- per-head elementwise stage 2 -------------------------
__global__ void ew2_kernel(const float* __restrict__ w0, const float* __restrict__ a0,
                           const float* __restrict__ v0, const float* __restrict__ kkw,
                           const float* __restrict__ kaw, const float* __restrict__ vfirst) {
    int bt = blockIdx.x / Hn;
    int h  = blockIdx.x % Hn;
    int n  = threadIdx.x;          // 0..63
    int c  = h * Nn + n;
    size_t idx = (size_t)bt * Cn + c;
    int b = bt / Tn, t = bt % Tn;
    size_t pb = ((size_t)(b * Hn + h) * Tn + t) * 384;

    __shared__ float red[64];
    float kraw = g_k[idx];
    float kkp = kraw * kkw[c];
    red[n] = kkp * kkp;
    __syncthreads();
#pragma unroll
    for (int s = 32; s > 0; s >>= 1) { if (n < s) red[n] += red[n + s]; __syncthreads(); }
    float norm = sqrtf(red[0]);
    float kkn = kkp / fmaxf(norm, 1e-12f);

    float av = 1.f / (1.f + expf(-(a0[c] + g_za[idx])));
    float xw = -(w0[c] + g_w[idx]);
    float sp = (xw > 20.f) ? xw : log1pf(expf(xw));
    float wv = expf(-expf(-0.5f - sp));
    float vs = 1.f / (1.f + expf(-(v0[c] + g_zv[idx])));
    float vraw = g_v[idx];
    float vv = vraw + (vfirst[idx] - vraw) * vs;

    g_pack[pb +       n] = g_r[idx];
    g_pack[pb +  64 + n] = wv;
    g_pack[pb + 128 + n] = kraw * (1.f + (av - 1.f) * kaw[c]);
    g_pack[pb + 192 + n] = vv;
    g_pack[pb + 256 + n] = -kkn;
    g_pack[pb + 320 + n] = kkn * av;
}

// ------------------------- WKV7 scan: 2 blocks per (b,h), float4 smem -------------
// grid = 2*B*H blocks; 128 threads. Block handles v-rows [vh*32, vh*32+32).
// Thread (v_local = tid>>2, kq = tid&3) owns S[v][16*kq .. 16*kq+15].
__global__ void __launch_bounds__(128) wkv7_scan() {
    const int bh = blockIdx.x >> 1;
    const int vh = blockIdx.x & 1;
    const int b = bh / Hn, h = bh % Hn;
    const int tid = threadIdx.x;
    const int v_local = tid >> 2;
    const int kq = tid & 3;
    const int v = vh * 32 + v_local;

    float S[16];
#pragma unroll
    for (int i = 0; i < 16; i++) S[i] = 0.f;

    // float4 smem: [buf][96]; float offsets: r=0,w=64,k=128,v=192,ah=256,bh=320
    __shared__ float4 sm4[2][96];
    const float4* pk4 = (const float4*)(g_pack + (size_t)bh * Tn * 384);
    size_t ybase = (size_t)b * Tn * Cn + (size_t)h * Nn + v;

    float4 pre;
    if (tid < 96) pre = pk4[tid];

    const int kb4 = kq * 4;   // float4 index of this thread's k-quad base
    int buf = 0;
    for (int t = 0; t < Tn; t++) {
        if (tid < 96) sm4[buf][tid] = pre;
        __syncthreads();

        if (t + 1 < Tn && tid < 96) pre = pk4[(size_t)(t + 1) * 96 + tid];

        const float4* r4  = &sm4[buf][0  + kb4];
        const float4* w4  = &sm4[buf][16 + kb4];
        const float4* k4  = &sm4[buf][32 + kb4];
        const float4* ah4 = &sm4[buf][64 + kb4];
        const float4* bh4 = &sm4[buf][80 + kb4];
        const float vv = ((const float*)&sm4[buf][48])[v];

        // sa = sum_k S[v][k] * ah[k] over this thread's 16 k's, then reduce over kq
        float4 A0 = ah4[0], A1 = ah4[1], A2 = ah4[2], A3 = ah4[3];
        float sa0 = S[0] * A0.x, sa1 = S[4] * A1.x, sa2 = S[8] * A2.x, sa3 = S[12] * A3.x;
        sa0 = fmaf(S[1], A0.y, sa0); sa1 = fmaf(S[5], A1.y, sa1);
        sa2 = fmaf(S[9], A2.y, sa2); sa3 = fmaf(S[13], A3.y, sa3);
        sa0 = fmaf(S[2], A0.z, sa0); sa1 = fmaf(S[6], A1.z, sa1);
        sa2 = fmaf(S[10], A2.z, sa2); sa3 = fmaf(S[14], A3.z, sa3);
        sa0 = fmaf(S[3], A0.w, sa0); sa1 = fmaf(S[7], A1.w, sa1);
        sa2 = fmaf(S[11], A2.w, sa2); sa3 = fmaf(S[15], A3.w, sa3);
        float sa = (sa0 + sa1) + (sa2 + sa3);
        sa += __shfl_xor_sync(0xffffffffu, sa, 1);
        sa += __shfl_xor_sync(0xffffffffu, sa, 2);

        float y0 = 0.f, y1 = 0.f, y2 = 0.f, y3 = 0.f;
#pragma unroll
        for (int j = 0; j < 4; j++) {
            float4 W = w4[j], Bv = bh4[j], Kv = k4[j], R = r4[j];
            S[j*4+0] = fmaf(S[j*4+0], W.x, fmaf(sa, Bv.x, vv * Kv.x));
            S[j*4+1] = fmaf(S[j*4+1], W.y, fmaf(sa, Bv.y, vv * Kv.y));
            S[j*4+2] = fmaf(S[j*4+2], W.z, fmaf(sa, Bv.z, vv * Kv.z));
            S[j*4+3] = fmaf(S[j*4+3], W.w, fmaf(sa, Bv.w, vv * Kv.w));
            y0 = fmaf(S[j*4+0], R.x, y0);
            y1 = fmaf(S[j*4+1], R.y, y1);
            y2 = fmaf(S[j*4+2], R.z, y2);
            y3 = fmaf(S[j*4+3], R.w, y3);
        }
        float y = (y0 + y1) + (y2 + y3);
        y += __shfl_xor_sync(0xffffffffu, y, 1);
        y += __shfl_xor_sync(0xffffffffu, y, 2);
        if (kq == 0) g_y[ybase + (size_t)t * Cn] = y;
        buf ^= 1;
        __syncthreads();
    }
}

// ------------------------- groupnorm + rk residual + gate -------------------------
__global__ void gn_kernel(const float* __restrict__ r_k, const float* __restrict__ gnw,
                          const float* __restrict__ gnb) {
    int bt = blockIdx.x / Hn;
    int h  = blockIdx.x % Hn;
    int n  = threadIdx.x;
    int c  = h * Nn + n;
    size_t idx = (size_t)bt * Cn + c;
    int b = bt / Tn, t = bt % Tn;
    size_t pb = ((size_t)(b * Hn + h) * Tn + t) * 384;

    __shared__ float red[64];
    float yv = g_y[idx];
    red[n] = yv;
    __syncthreads();
#pragma unroll
    for (int s = 32; s > 0; s >>= 1) { if (n < s) red[n] += red[n + s]; __syncthreads(); }
    float mu = red[0] * (1.f / 64.f);
    __syncthreads();

    float d = yv - mu;
    red[n] = d * d;
    __syncthreads();
#pragma unroll
    for (int s = 32; s > 0; s >>= 1) { if (n < s) red[n] += red[n + s]; __syncthreads(); }
    float var = red[0] * (1.f / 64.f);
    __syncthreads();

    float yn = d * rsqrtf(var + (float)(Nn * 1e-5)) * gnw[c] + gnb[c];

    float rr = g_pack[pb + n];
    float kk = g_pack[pb + 128 + n];
    float vv = g_pack[pb + 192 + n];
    float dp = rr * kk * r_k[c];
    red[n] = dp;
    __syncthreads();
#pragma unroll
    for (int s = 32; s > 0; s >>= 1) { if (n < s) red[n] += red[n + s]; __syncthreads(); }
    float dot = red[0];

    g_op[idx] = (yn + dot * vv) * g_g[idx];
}

// ------------------------- launch -------------------------
extern "C" void kernel_launch(void* const* d_in, const int* in_sizes, int n_in,
                              void* d_out, int out_size) {
    (void)in_sizes; (void)n_in; (void)out_size;
    const float* x      = (const float*)d_in[0];
    const float* vfirst = (const float*)d_in[1];
    const float* x_r = (const float*)d_in[2];
    const float* x_w = (const float*)d_in[3];
    const float* x_k = (const float*)d_in[4];
    const float* x_v = (const float*)d_in[5];
    const float* x_a = (const float*)d_in[6];
    const float* x_g = (const float*)d_in[7];
    const float* w0  = (const float*)d_in[8];
    const float* w1  = (const float*)d_in[9];
    const float* w2  = (const float*)d_in[10];
    const float* a0  = (const float*)d_in[11];
    const float* a1  = (const float*)d_in[12];
    const float* a2  = (const float*)d_in[13];
    const float* v0  = (const float*)d_in[14];
    const float* v1  = (const float*)d_in[15];
    const float* v2  = (const float*)d_in[16];
    const float* g1  = (const float*)d_in[17];
    const float* g2  = (const float*)d_in[18];
    const float* k_k = (const float*)d_in[19];
    const float* k_a = (const float*)d_in[20];
    const float* r_k = (const float*)d_in[21];
    const float* W_r = (const float*)d_in[22];
    const float* W_k = (const float*)d_in[23];
    const float* W_v = (const float*)d_in[24];
    const float* W_o = (const float*)d_in[25];
    const float* gnw = (const float*)d_in[26];
    const float* gnb = (const float*)d_in[27];
    float* out = (float*)d_out;

    float *p_xr, *p_xw, *p_xk, *p_xv, *p_xa, *p_xg;
    float *p_r, *p_k, *p_v, *p_w, *p_za, *p_zv, *p_g, *p_op;
    float *p_tw, *p_ta, *p_tv, *p_tg;
    cudaGetSymbolAddress((void**)&p_xr, g_xr);
    cudaGetSymbolAddress((void**)&p_xw, g_xw);
    cudaGetSymbolAddress((void**)&p_xk, g_xk);
    cudaGetSymbolAddress((void**)&p_xv, g_xv);
    cudaGetSymbolAddress((void**)&p_xa, g_xa);
    cudaGetSymbolAddress((void**)&p_xg, g_xg);
    cudaGetSymbolAddress((void**)&p_r,  g_r);
    cudaGetSymbolAddress((void**)&p_k,  g_k);
    cudaGetSymbolAddress((void**)&p_v,  g_v);
    cudaGetSymbolAddress((void**)&p_w,  g_w);
    cudaGetSymbolAddress((void**)&p_za, g_za);
    cudaGetSymbolAddress((void**)&p_zv, g_zv);
    cudaGetSymbolAddress((void**)&p_g,  g_g);
    cudaGetSymbolAddress((void**)&p_op, g_op);
    cudaGetSymbolAddress((void**)&p_tw, g_tw);
    cudaGetSymbolAddress((void**)&p_ta, g_ta);
    cudaGetSymbolAddress((void**)&p_tv, g_tv);
    cudaGetSymbolAddress((void**)&p_tg, g_tg);

    // 1) token shift + mixes
    mix_kernel<<<(BTn * Cn / 4 + 255) / 256, 256>>>(
        (const float4*)x, (const float4*)x_r, (const float4*)x_w, (const float4*)x_k,
        (const float4*)x_v, (const float4*)x_a, (const float4*)x_g);

    // 2) r/k/v projections (batched over z)
    {
        GB p = {};
        p.A[0] = p_xr; p.A[1] = p_xk; p.A[2] = p_xv;
        p.Bw[0] = W_r; p.Bw[1] = W_k; p.Bw[2] = W_v;
        p.C[0] = p_r;  p.C[1] = p_k;  p.C[2] = p_v;
        for (int z = 0; z < 3; z++) { p.N[z] = Cn; p.K[z] = Cn; p.act[z] = 0; }
        gemm_pipe<128, 128, 64, 32><<<dim3(16, 16, 3), 256>>>(p);
    }

    // 3a) LoRA ups (skinny N, batched)
    {
        GB p = {};
        p.A[0] = p_xw; p.A[1] = p_xa; p.A[2] = p_xv; p.A[3] = p_xg;
        p.Bw[0] = w1;  p.Bw[1] = a1;  p.Bw[2] = v1;  p.Bw[3] = g1;
        p.C[0] = p_tw; p.C[1] = p_ta; p.C[2] = p_tv; p.C[3] = p_tg;
        p.N[0] = 96; p.N[1] = 96; p.N[2] = 64; p.N[3] = 256;
        for (int z = 0; z < 4; z++) p.K[z] = Cn;
        p.act[0] = 1; p.act[1] = 0; p.act[2] = 0; p.act[3] = 2;
        gemm_pipe<64, 32, 32, 16><<<dim3(8, BTn / 64, 4), 128>>>(p);
    }

    // 3b) LoRA downs (N=2048, small K, batched)
    {
        GB p = {};
        p.A[0] = p_tw; p.A[1] = p_ta; p.A[2] = p_tv; p.A[3] = p_tg;
        p.Bw[0] = w2;  p.Bw[1] = a2;  p.Bw[2] = v2;  p.Bw[3] = g2;
        p.C[0] = p_w;  p.C[1] = p_za; p.C[2] = p_zv; p.C[3] = p_g;
        p.K[0] = 96; p.K[1] = 96; p.K[2] = 64; p.K[3] = 256;
        for (int z = 0; z < 4; z++) { p.N[z] = Cn; p.act[z] = 0; }
        gemm_pipe<128, 128, 64, 32><<<dim3(16, 16, 4), 256>>>(p);
    }

    // 4) per-head elementwise -> packed scan operands
    ew2_kernel<<<BTn * Hn, 64>>>(w0, a0, v0, k_k, k_a, vfirst);

    // 5) WKV7 scan (2 blocks per head)
    wkv7_scan<<<2 * Bn * Hn, 128>>>();

    // 6) groupnorm + residual + gate
    gn_kernel<<<BTn * Hn, 64>>>(r_k, gnw, gnb);

    // 7) output projection
    {
        GB p = {};
        p.A[0] = p_op; p.Bw[0] = W_o; p.C[0] = out;
        p.N[0] = Cn; p.K[0] = Cn; p.act[0] = 0;
        gemm_pipe<128, 128, 64, 32><<<dim3(16, 16, 1), 256>>>(p);
    }
}

// round 5
// speedup vs baseline: 4.5067x; 1.1686x over previous
#include <cuda_runtime.h>
#include <math.h>

// Problem constants
#define Bn 2
#define Tn 1024
#define Cn 2048
#define Hn 32
#define Nn 64
#define BTn (Bn*Tn)

// ------------------------- scratch (static device globals) -------------------------
__device__ float g_xr[BTn*Cn];
__device__ float g_xw[BTn*Cn];
__device__ float g_xk[BTn*Cn];
__device__ float g_xv[BTn*Cn];
__device__ float g_xa[BTn*Cn];
__device__ float g_xg[BTn*Cn];
__device__ float g_r [BTn*Cn];
__device__ float g_k [BTn*Cn];
__device__ float g_v [BTn*Cn];
__device__ float g_w [BTn*Cn];
__device__ float g_za[BTn*Cn];
__device__ float g_zv[BTn*Cn];
__device__ float g_g [BTn*Cn];
__device__ float g_y [BTn*Cn];
__device__ float g_op[BTn*Cn];
__device__ float g_tw[BTn*96];
__device__ float g_ta[BTn*96];
__device__ float g_tv[BTn*64];
__device__ float g_tg[BTn*256];
// packed scan operands: [B*H][T][6*64]  order: r,w,k,v,ah,bh
__device__ float g_pack[(size_t)Bn*Hn*Tn*384];

// ------------------------- helpers -------------------------
__device__ __forceinline__ unsigned f2tf32(float f) {
    unsigned u;
    asm("cvt.rna.tf32.f32 %0, %1;" : "=r"(u) : "f"(f));
    return u;
}

__device__ __forceinline__ void mma_tf32(float* d, const unsigned* a, const unsigned* b) {
    asm volatile(
        "mma.sync.aligned.m16n8k8.row.col.f32.tf32.tf32.f32 "
        "{%0,%1,%2,%3}, {%4,%5,%6,%7}, {%8,%9}, {%0,%1,%2,%3};"
        : "+f"(d[0]), "+f"(d[1]), "+f"(d[2]), "+f"(d[3])
        : "r"(a[0]), "r"(a[1]), "r"(a[2]), "r"(a[3]),
          "r"(b[0]), "r"(b[1]));
}

__device__ __forceinline__ void cp16(void* smem, const void* g) {
    unsigned saddr = (unsigned)__cvta_generic_to_shared(smem);
    asm volatile("cp.async.cg.shared.global [%0], [%1], 16;" :: "r"(saddr), "l"(g));
}
__device__ __forceinline__ void cp_commit() { asm volatile("cp.async.commit_group;"); }
__device__ __forceinline__ void cp_wait1()  { asm volatile("cp.async.wait_group 1;"); }

__device__ __forceinline__ float warp_sum(float v) {
#pragma unroll
    for (int o = 16; o > 0; o >>= 1) v += __shfl_xor_sync(0xffffffffu, v, o);
    return v;
}

// ------------------------- batched, pipelined tf32 GEMM -------------------------
struct GB {
    const float* A[4];
    const float* Bw[4];
    float*       C[4];
    int N[4];
    int K[4];
    int act[4];   // 0=none 1=tanh 2=sigmoid
};

template<int BM, int BN, int WM, int WN>
__global__ void __launch_bounds__((BM/WM)*(BN/WN)*32)
gemm_pipe(GB p) {
    constexpr int KT = 16;
    constexpr int WARPS_M = BM / WM;
    constexpr int WARPS_N = BN / WN;
    constexpr int NTHREADS = WARPS_M * WARPS_N * 32;
    constexpr int MT = WM / 16;
    constexpr int NT_ = WN / 8;
    constexpr int ASTR = KT + 4;
    constexpr int BSTR = BN + 8;

    __shared__ float Asm[2][BM][ASTR];
    __shared__ float Bsm[2][KT][BSTR];

    const int z = blockIdx.z;
    const float* A = p.A[z];
    const float* B = p.Bw[z];
    float* C = p.C[z];
    const int N = p.N[z], K = p.K[z], act = p.act[z];
    const int bn = blockIdx.x * BN;
    if (bn >= N) return;
    const int bm = blockIdx.y * BM;

    const int tid = threadIdx.x;
    const int wid = tid >> 5, lane = tid & 31;
    const int gid = lane >> 2, tig = lane & 3;
    const int warp_m = wid / WARPS_N, warp_n = wid % WARPS_N;
    const int wm = warp_m * WM, wn = warp_n * WN;

    float acc[MT][NT_][4];
#pragma unroll
    for (int i = 0; i < MT; i++)
#pragma unroll
        for (int j = 0; j < NT_; j++)
#pragma unroll
            for (int q = 0; q < 4; q++) acc[i][j][q] = 0.f;

    auto load_stage = [&](int s, int k0) {
#pragma unroll
        for (int i = 0; i < (BM * 4) / NTHREADS; i++) {
            int id = tid + i * NTHREADS;
            int m = id >> 2, kc = (id & 3) * 4;
            cp16(&Asm[s][m][kc], A + (size_t)(bm + m) * K + k0 + kc);
        }
#pragma unroll
        for (int i = 0; i < (KT * BN / 4) / NTHREADS; i++) {
            int id = tid + i * NTHREADS;
            int kr = id / (BN / 4), nq = (id % (BN / 4)) * 4;
            cp16(&Bsm[s][kr][nq], B + (size_t)(k0 + kr) * N + bn + nq);
        }
    };

    const int nk = K / KT;
    load_stage(0, 0);
    cp_commit();

    for (int kt = 0; kt < nk; kt++) {
        __syncthreads();
        if (kt + 1 < nk) load_stage((kt + 1) & 1, (kt + 1) * KT);
        cp_commit();
        cp_wait1();
        __syncthreads();

        const int s = kt & 1;
#pragma unroll
        for (int kk = 0; kk < KT; kk += 8) {
            unsigned af[MT][4], bf[NT_][2];
#pragma unroll
            for (int mt = 0; mt < MT; mt++) {
                int rm = wm + mt * 16 + gid;
                af[mt][0] = f2tf32(Asm[s][rm][kk + tig]);
                af[mt][1] = f2tf32(Asm[s][rm + 8][kk + tig]);
                af[mt][2] = f2tf32(Asm[s][rm][kk + tig + 4]);
                af[mt][3] = f2tf32(Asm[s][rm + 8][kk + tig + 4]);
            }
#pragma unroll
            for (int nt = 0; nt < NT_; nt++) {
                int cn = wn + nt * 8 + gid;
                bf[nt][0] = f2tf32(Bsm[s][kk + tig][cn]);
                bf[nt][1] = f2tf32(Bsm[s][kk + tig + 4][cn]);
            }
#pragma unroll
            for (int mt = 0; mt < MT; mt++)
#pragma unroll
                for (int nt = 0; nt < NT_; nt++)
                    mma_tf32(acc[mt][nt], af[mt], bf[nt]);
        }
    }

#pragma unroll
    for (int mt = 0; mt < MT; mt++) {
#pragma unroll
        for (int nt = 0; nt < NT_; nt++) {
            int r0 = bm + wm + mt * 16 + gid;
            int c = bn + wn + nt * 8 + tig * 2;
            float v0 = acc[mt][nt][0], v1 = acc[mt][nt][1];
            float v2 = acc[mt][nt][2], v3 = acc[mt][nt][3];
            if (act == 1) {
                v0 = tanhf(v0); v1 = tanhf(v1); v2 = tanhf(v2); v3 = tanhf(v3);
            } else if (act == 2) {
                v0 = 1.f / (1.f + expf(-v0)); v1 = 1.f / (1.f + expf(-v1));
                v2 = 1.f / (1.f + expf(-v2)); v3 = 1.f / (1.f + expf(-v3));
            }
            *(float2*)(C + (size_t)r0 * N + c) = make_float2(v0, v1);
            *(float2*)(C + (size_t)(r0 + 8) * N + c) = make_float2(v2, v3);
        }
    }
}

// ------------------------- token shift + 6 mixes (float4) -------------------------
__global__ void mix_kernel(const float4* __restrict__ x,
                           const float4* __restrict__ cr, const float4* __restrict__ cw,
                           const float4* __restrict__ ck, const float4* __restrict__ cv,
                           const float4* __restrict__ ca, const float4* __restrict__ cg) {
    size_t i = (size_t)blockIdx.x * blockDim.x + threadIdx.x;
    constexpr size_t TOT = (size_t)BTn * Cn / 4;
    constexpr int C4 = Cn / 4;
    if (i >= TOT) return;
    int c = (int)(i % C4);
    size_t bt = i / C4;
    int t = (int)(bt % Tn);
    float4 xc = x[i];
    float4 prev = (t == 0) ? make_float4(0.f, 0.f, 0.f, 0.f) : x[i - C4];
    float4 dx = make_float4(prev.x - xc.x, prev.y - xc.y, prev.z - xc.z, prev.w - xc.w);
#define MIXO(dst, coef) { \
    float4 cc = coef[c]; \
    ((float4*)dst)[i] = make_float4(fmaf(dx.x, cc.x, xc.x), fmaf(dx.y, cc.y, xc.y), \
                                    fmaf(dx.z, cc.z, xc.z), fmaf(dx.w, cc.w, xc.w)); }
    MIXO(g_xr, cr); MIXO(g_xw, cw); MIXO(g_xk, ck);
    MIXO(g_xv, cv); MIXO(g_xa, ca); MIXO(g_xg, cg);
#undef MIXO
}

// ------------------------- per-head elementwise stage 2 (warp per head) -----------
// 256 threads = 8 warps, one warp per (bt,h); each lane owns channels n=lane, n+32.
__global__ void __launch_bounds__(256) ew2_kernel(
        const float* __restrict__ w0, const float* __restrict__ a0,
        const float* __restrict__ v0, const float* __restrict__ kkw,
        const float* __restrict__ kaw, const float* __restrict__ vfirst) {
    int w = blockIdx.x * 8 + (threadIdx.x >> 5);
    int lane = threadIdx.x & 31;
    int bt = w / Hn, h = w % Hn;
    int b = bt / Tn, t = bt % Tn;
    size_t pb = ((size_t)(b * Hn + h) * Tn + t) * 384;
    size_t base = (size_t)bt * Cn + h * Nn;

    float kraw[2], kkp[2], av[2], vv[2], wv[2];
#pragma unroll
    for (int j = 0; j < 2; j++) {
        int n = lane + 32 * j;
        int c = h * Nn + n;
        size_t idx = base + n;
        kraw[j] = g_k[idx];
        kkp[j] = kraw[j] * kkw[c];
        av[j] = 1.f / (1.f + expf(-(a0[c] + g_za[idx])));
        float xw = -(w0[c] + g_w[idx]);
        float sp = (xw > 20.f) ? xw : log1pf(expf(xw));
        wv[j] = expf(-expf(-0.5f - sp));
        float vs = 1.f / (1.f + expf(-(v0[c] + g_zv[idx])));
        float vraw = g_v[idx];
        vv[j] = vraw + (vfirst[idx] - vraw) * vs;
    }
    float nrm2 = warp_sum(kkp[0] * kkp[0] + kkp[1] * kkp[1]);
    float inv = 1.f / fmaxf(sqrtf(nrm2), 1e-12f);

#pragma unroll
    for (int j = 0; j < 2; j++) {
        int n = lane + 32 * j;
        int c = h * Nn + n;
        size_t idx = base + n;
        float kkn = kkp[j] * inv;
        g_pack[pb +       n] = g_r[idx];
        g_pack[pb +  64 + n] = wv[j];
        g_pack[pb + 128 + n] = kraw[j] * (1.f + (av[j] - 1.f) * kaw[c]);
        g_pack[pb + 192 + n] = vv[j];
        g_pack[pb + 256 + n] = -kkn;
        g_pack[pb + 320 + n] = kkn * av[j];
    }
}

// ------------------------- WKV7 scan: 4-step groups, cp.async prefetch ------------
// grid = 2*B*H blocks; 128 threads. Block handles v-rows [vh*32, vh*32+32).
// Thread (v_local = tid>>2, kq = tid&3) owns S[v][16*kq .. 16*kq+15].
__global__ void __launch_bounds__(128) wkv7_scan() {
    const int bh = blockIdx.x >> 1;
    const int vh = blockIdx.x & 1;
    const int b = bh / Hn, h = bh % Hn;
    const int tid = threadIdx.x;
    const int v_local = tid >> 2;
    const int kq = tid & 3;
    const int v = vh * 32 + v_local;

    float S[16];
#pragma unroll
    for (int i = 0; i < 16; i++) S[i] = 0.f;

    // [buf][step][96] float4; float offsets within step: r=0,w=64,k=128,v=192,ah=256,bh=320
    __shared__ float4 sm4[2][4][96];
    const float4* pk4 = (const float4*)(g_pack + (size_t)bh * Tn * 384);
    size_t ybase = (size_t)b * Tn * Cn + (size_t)h * Nn + v;

    auto load_group = [&](int buf, int g) {
#pragma unroll
        for (int i = 0; i < 3; i++) {
            int id = tid + i * 128;           // 0..383
            int st = id / 96, off = id % 96;
            cp16(&sm4[buf][st][off], pk4 + (size_t)(g * 4 + st) * 96 + off);
        }
    };

    load_group(0, 0); cp_commit();
    load_group(1, 1); cp_commit();

    const int kb4 = kq * 4;
    constexpr int NG = Tn / 4;   // 256 groups

    for (int g = 0; g < NG; g++) {
        cp_wait1();
        __syncthreads();
        const int buf = g & 1;

#pragma unroll
        for (int st = 0; st < 4; st++) {
            const float4* r4  = &sm4[buf][st][0  + kb4];
            const float4* w4  = &sm4[buf][st][16 + kb4];
            const float4* k4  = &sm4[buf][st][32 + kb4];
            const float4* ah4 = &sm4[buf][st][64 + kb4];
            const float4* bh4 = &sm4[buf][st][80 + kb4];
            const float vv = ((const float*)&sm4[buf][st][48])[v];

            float4 A0 = ah4[0], A1 = ah4[1], A2 = ah4[2], A3 = ah4[3];
            float sa0 = S[0] * A0.x, sa1 = S[4] * A1.x, sa2 = S[8] * A2.x, sa3 = S[12] * A3.x;
            sa0 = fmaf(S[1], A0.y, sa0); sa1 = fmaf(S[5], A1.y, sa1);
            sa2 = fmaf(S[9], A2.y, sa2); sa3 = fmaf(S[13], A3.y, sa3);
            sa0 = fmaf(S[2], A0.z, sa0); sa1 = fmaf(S[6], A1.z, sa1);
            sa2 = fmaf(S[10], A2.z, sa2); sa3 = fmaf(S[14], A3.z, sa3);
            sa0 = fmaf(S[3], A0.w, sa0); sa1 = fmaf(S[7], A1.w, sa1);
            sa2 = fmaf(S[11], A2.w, sa2); sa3 = fmaf(S[15], A3.w, sa3);
            float sa = (sa0 + sa1) + (sa2 + sa3);
            sa += __shfl_xor_sync(0xffffffffu, sa, 1);
            sa += __shfl_xor_sync(0xffffffffu, sa, 2);

            float y0 = 0.f, y1 = 0.f, y2 = 0.f, y3 = 0.f;
#pragma unroll
            for (int j = 0; j < 4; j++) {
                float4 W = w4[j], Bv = bh4[j], Kv = k4[j], R = r4[j];
                S[j*4+0] = fmaf(S[j*4+0], W.x, fmaf(sa, Bv.x, vv * Kv.x));
                S[j*4+1] = fmaf(S[j*4+1], W.y, fmaf(sa, Bv.y, vv * Kv.y));
                S[j*4+2] = fmaf(S[j*4+2], W.z, fmaf(sa, Bv.z, vv * Kv.z));
                S[j*4+3] = fmaf(S[j*4+3], W.w, fmaf(sa, Bv.w, vv * Kv.w));
                y0 = fmaf(S[j*4+0], R.x, y0);
                y1 = fmaf(S[j*4+1], R.y, y1);
                y2 = fmaf(S[j*4+2], R.z, y2);
                y3 = fmaf(S[j*4+3], R.w, y3);
            }
            float y = (y0 + y1) + (y2 + y3);
            y += __shfl_xor_sync(0xffffffffu, y, 1);
            y += __shfl_xor_sync(0xffffffffu, y, 2);
            if (kq == 0) g_y[ybase + (size_t)(g * 4 + st) * Cn] = y;
        }

        __syncthreads();   // all readers done with sm4[buf] before overwrite
        if (g + 2 < NG) load_group(buf, g + 2);
        cp_commit();
    }
}

// ------------------------- groupnorm + rk residual + gate (warp per head) ---------
__global__ void __launch_bounds__(256) gn_kernel(
        const float* __restrict__ r_k, const float* __restrict__ gnw,
        const float* __restrict__ gnb) {
    int w = blockIdx.x * 8 + (threadIdx.x >> 5);
    int lane = threadIdx.x & 31;
    int bt = w / Hn, h = w % Hn;
    int b = bt / Tn, t = bt % Tn;
    size_t pb = ((size_t)(b * Hn + h) * Tn + t) * 384;
    size_t base = (size_t)bt * Cn + h * Nn;

    float yv[2], rr[2], kk[2], vv[2];
#pragma unroll
    for (int j = 0; j < 2; j++) {
        int n = lane + 32 * j;
        yv[j] = g_y[base + n];
        rr[j] = g_pack[pb + n];
        kk[j] = g_pack[pb + 128 + n];
        vv[j] = g_pack[pb + 192 + n];
    }
    float mu = warp_sum(yv[0] + yv[1]) * (1.f / 64.f);
    float d0 = yv[0] - mu, d1 = yv[1] - mu;
    float var = warp_sum(d0 * d0 + d1 * d1) * (1.f / 64.f);
    float rs = rsqrtf(var + (float)(Nn * 1e-5));

    float dp0, dp1;
    {
        int c0 = h * Nn + lane, c1 = c0 + 32;
        dp0 = rr[0] * kk[0] * r_k[c0];
        dp1 = rr[1] * kk[1] * r_k[c1];
    }
    float dot = warp_sum(dp0 + dp1);

#pragma unroll
    for (int j = 0; j < 2; j++) {
        int n = lane + 32 * j;
        int c = h * Nn + n;
        size_t idx = base + n;
        float d = (j == 0) ? d0 : d1;
        float yn = d * rs * gnw[c] + gnb[c];
        g_op[idx] = (yn + dot * vv[j]) * g_g[idx];
    }
}

// ------------------------- launch -------------------------
extern "C" void kernel_launch(void* const* d_in, const int* in_sizes, int n_in,
                              void* d_out, int out_size) {
    (void)in_sizes; (void)n_in; (void)out_size;
    const float* x      = (const float*)d_in[0];
    const float* vfirst = (const float*)d_in[1];
    const float* x_r = (const float*)d_in[2];
    const float* x_w = (const float*)d_in[3];
    const float* x_k = (const float*)d_in[4];
    const float* x_v = (const float*)d_in[5];
    const float* x_a = (const float*)d_in[6];
    const float* x_g = (const float*)d_in[7];
    const float* w0  = (const float*)d_in[8];
    const float* w1  = (const float*)d_in[9];
    const float* w2  = (const float*)d_in[10];
    const float* a0  = (const float*)d_in[11];
    const float* a1  = (const float*)d_in[12];
    const float* a2  = (const float*)d_in[13];
    const float* v0  = (const float*)d_in[14];
    const float* v1  = (const float*)d_in[15];
    const float* v2  = (const float*)d_in[16];
    const float* g1  = (const float*)d_in[17];
    const float* g2  = (const float*)d_in[18];
    const float* k_k = (const float*)d_in[19];
    const float* k_a = (const float*)d_in[20];
    const float* r_k = (const float*)d_in[21];
    const float* W_r = (const float*)d_in[22];
    const float* W_k = (const float*)d_in[23];
    const float* W_v = (const float*)d_in[24];
    const float* W_o = (const float*)d_in[25];
    const float* gnw = (const float*)d_in[26];
    const float* gnb = (const float*)d_in[27];
    float* out = (float*)d_out;

    float *p_xr, *p_xw, *p_xk, *p_xv, *p_xa, *p_xg;
    float *p_r, *p_k, *p_v, *p_w, *p_za, *p_zv, *p_g, *p_op;
    float *p_tw, *p_ta, *p_tv, *p_tg;
    cudaGetSymbolAddress((void**)&p_xr, g_xr);
    cudaGetSymbolAddress((void**)&p_xw, g_xw);
    cudaGetSymbolAddress((void**)&p_xk, g_xk);
    cudaGetSymbolAddress((void**)&p_xv, g_xv);
    cudaGetSymbolAddress((void**)&p_xa, g_xa);
    cudaGetSymbolAddress((void**)&p_xg, g_xg);
    cudaGetSymbolAddress((void**)&p_r,  g_r);
    cudaGetSymbolAddress((void**)&p_k,  g_k);
    cudaGetSymbolAddress((void**)&p_v,  g_v);
    cudaGetSymbolAddress((void**)&p_w,  g_w);
    cudaGetSymbolAddress((void**)&p_za, g_za);
    cudaGetSymbolAddress((void**)&p_zv, g_zv);
    cudaGetSymbolAddress((void**)&p_g,  g_g);
    cudaGetSymbolAddress((void**)&p_op, g_op);
    cudaGetSymbolAddress((void**)&p_tw, g_tw);
    cudaGetSymbolAddress((void**)&p_ta, g_ta);
    cudaGetSymbolAddress((void**)&p_tv, g_tv);
    cudaGetSymbolAddress((void**)&p_tg, g_tg);

    // 1) token shift + mixes
    mix_kernel<<<(BTn * Cn / 4 + 255) / 256, 256>>>(
        (const float4*)x, (const float4*)x_r, (const float4*)x_w, (const float4*)x_k,
        (const float4*)x_v, (const float4*)x_a, (const float4*)x_g);

    // 2) r/k/v projections (batched over z)
    {
        GB p = {};
        p.A[0] = p_xr; p.A[1] = p_xk; p.A[2] = p_xv;
        p.Bw[0] = W_r; p.Bw[1] = W_k; p.Bw[2] = W_v;
        p.C[0] = p_r;  p.C[1] = p_k;  p.C[2] = p_v;
        for (int z = 0; z < 3; z++) { p.N[z] = Cn; p.K[z] = Cn; p.act[z] = 0; }
        gemm_pipe<128, 128, 64, 32><<<dim3(16, 16, 3), 256>>>(p);
    }

    // 3a) LoRA ups (skinny N, batched)
    {
        GB p = {};
        p.A[0] = p_xw; p.A[1] = p_xa; p.A[2] = p_xv; p.A[3] = p_xg;
        p.Bw[0] = w1;  p.Bw[1] = a1;  p.Bw[2] = v1;  p.Bw[3] = g1;
        p.C[0] = p_tw; p.C[1] = p_ta; p.C[2] = p_tv; p.C[3] = p_tg;
        p.N[0] = 96; p.N[1] = 96; p.N[2] = 64; p.N[3] = 256;
        for (int z = 0; z < 4; z++) p.K[z] = Cn;
        p.act[0] = 1; p.act[1] = 0; p.act[2] = 0; p.act[3] = 2;
        gemm_pipe<64, 32, 32, 16><<<dim3(8, BTn / 64, 4), 128>>>(p);
    }

    // 3b) LoRA downs (N=2048, small K, batched)
    {
        GB p = {};
        p.A[0] = p_tw; p.A[1] = p_ta; p.A[2] = p_tv; p.A[3] = p_tg;
        p.Bw[0] = w2;  p.Bw[1] = a2;  p.Bw[2] = v2;  p.Bw[3] = g2;
        p.C[0] = p_w;  p.C[1] = p_za; p.C[2] = p_zv; p.C[3] = p_g;
        p.K[0] = 96; p.K[1] = 96; p.K[2] = 64; p.K[3] = 256;
        for (int z = 0; z < 4; z++) { p.N[z] = Cn; p.act[z] = 0; }
        gemm_pipe<128, 128, 64, 32><<<dim3(16, 16, 4), 256>>>(p);
    }

    // 4) per-head elementwise -> packed scan operands (warp per head)
    ew2_kernel<<<BTn * Hn / 8, 256>>>(w0, a0, v0, k_k, k_a, vfirst);

    // 5) WKV7 scan (2 blocks per head, 4-step groups)
    wkv7_scan<<<2 * Bn * Hn, 128>>>();

    // 6) groupnorm + residual + gate (warp per head)
    gn_kernel<<<BTn * Hn / 8, 256>>>(r_k, gnw, gnb);

    // 7) output projection
    {
        GB p = {};
        p.A[0] = p_op; p.Bw[0] = W_o; p.C[0] = out;
        p.N[0] = Cn; p.K[0] = Cn; p.act[0] = 0;
        gemm_pipe<128, 128, 64, 32><<<dim3(16, 16, 1), 256>>>(p);
    }
}

// round 6
// speedup vs baseline: 4.7188x; 1.0471x over previous
#include <cuda_runtime.h>
#include <math.h>

// Problem constants
#define Bn 2
#define Tn 1024
#define Cn 2048
#define Hn 32
#define Nn 64
#define BTn (Bn*Tn)

// ------------------------- scratch (static device globals) -------------------------
__device__ float g_xr[BTn*Cn];
__device__ float g_xw[BTn*Cn];
__device__ float g_xk[BTn*Cn];
__device__ float g_xv[BTn*Cn];
__device__ float g_xa[BTn*Cn];
__device__ float g_xg[BTn*Cn];
__device__ float g_r [BTn*Cn];
__device__ float g_k [BTn*Cn];
__device__ float g_v [BTn*Cn];
__device__ float g_w [BTn*Cn];
__device__ float g_za[BTn*Cn];
__device__ float g_zv[BTn*Cn];
__device__ float g_g [BTn*Cn];
__device__ float g_y [BTn*Cn];
__device__ float g_op[BTn*Cn];
__device__ float g_tw[BTn*96];
__device__ float g_ta[BTn*96];
__device__ float g_tv[BTn*64];
__device__ float g_tg[BTn*256];
// packed scan operands: [B*H][T][6*64]  order: r,w,k,v,ah,bh
__device__ float g_pack[(size_t)Bn*Hn*Tn*384];
// pre-rounded (tf32) weights
__device__ float g_Wr[Cn*Cn];
__device__ float g_Wk[Cn*Cn];
__device__ float g_Wv[Cn*Cn];
__device__ float g_Wo[Cn*Cn];
__device__ float g_w1r[Cn*96];
__device__ float g_a1r[Cn*96];
__device__ float g_v1r[Cn*64];
__device__ float g_g1r[Cn*256];
__device__ float g_w2r[96*Cn];
__device__ float g_a2r[96*Cn];
__device__ float g_v2r[64*Cn];
__device__ float g_g2r[256*Cn];

// ------------------------- helpers -------------------------
__device__ __forceinline__ unsigned f2tf32(float f) {
    unsigned u;
    asm("cvt.rna.tf32.f32 %0, %1;" : "=r"(u) : "f"(f));
    return u;
}
__device__ __forceinline__ float rnd_tf32(float f) { return __uint_as_float(f2tf32(f)); }

__device__ __forceinline__ void mma_tf32(float* d, const unsigned* a, const unsigned* b) {
    asm volatile(
        "mma.sync.aligned.m16n8k8.row.col.f32.tf32.tf32.f32 "
        "{%0,%1,%2,%3}, {%4,%5,%6,%7}, {%8,%9}, {%0,%1,%2,%3};"
        : "+f"(d[0]), "+f"(d[1]), "+f"(d[2]), "+f"(d[3])
        : "r"(a[0]), "r"(a[1]), "r"(a[2]), "r"(a[3]),
          "r"(b[0]), "r"(b[1]));
}

__device__ __forceinline__ void cp16(void* smem, const void* g) {
    unsigned saddr = (unsigned)__cvta_generic_to_shared(smem);
    asm volatile("cp.async.cg.shared.global [%0], [%1], 16;" :: "r"(saddr), "l"(g));
}
__device__ __forceinline__ void cp_commit() { asm volatile("cp.async.commit_group;" ::: "memory"); }
__device__ __forceinline__ void cp_wait1()  { asm volatile("cp.async.wait_group 1;" ::: "memory"); }

__device__ __forceinline__ float warp_sum(float v) {
#pragma unroll
    for (int o = 16; o > 0; o >>= 1) v += __shfl_xor_sync(0xffffffffu, v, o);
    return v;
}

// ------------------------- weight rounding prepass -------------------------
struct RP {
    const float4* src[12];
    float4* dst[12];
    int n4[12];
};
__global__ void round_weights(RP p) {
    int zb = blockIdx.y;
    int i = blockIdx.x * blockDim.x + threadIdx.x;
    if (i >= p.n4[zb]) return;
    float4 v = p.src[zb][i];
    v.x = rnd_tf32(v.x); v.y = rnd_tf32(v.y);
    v.z = rnd_tf32(v.z); v.w = rnd_tf32(v.w);
    p.dst[zb][i] = v;
}

// ------------------------- batched 3-stage tf32 GEMM (pre-rounded operands) --------
struct GB {
    const float* A[4];
    const float* Bw[4];
    float*       C[4];
    int N[4];
    int K[4];
    int act[4];   // 0=none 1=tanh 2=sigmoid
    int rnd[4];   // round output to tf32?
};

template<int BM, int BN, int WM, int WN>
__global__ void __launch_bounds__((BM/WM)*(BN/WN)*32)
gemm3(GB p) {
    constexpr int KT = 16;
    constexpr int STG = 3;
    constexpr int WARPS_M = BM / WM;
    constexpr int WARPS_N = BN / WN;
    constexpr int NTHREADS = WARPS_M * WARPS_N * 32;
    constexpr int MT = WM / 16;
    constexpr int NT_ = WN / 8;
    constexpr int ASTR = KT + 4;
    constexpr int BSTR = BN + 8;

    extern __shared__ unsigned dsm[];
    unsigned (*Asm)[BM][ASTR] = (unsigned(*)[BM][ASTR])dsm;
    unsigned (*Bsm)[KT][BSTR] = (unsigned(*)[KT][BSTR])(dsm + STG * BM * ASTR);

    const int z = blockIdx.z;
    const float* A = p.A[z];
    const float* B = p.Bw[z];
    float* C = p.C[z];
    const int N = p.N[z], K = p.K[z], act = p.act[z], rd = p.rnd[z];
    const int bn = blockIdx.x * BN;
    if (bn >= N) return;
    const int bm = blockIdx.y * BM;

    const int tid = threadIdx.x;
    const int wid = tid >> 5, lane = tid & 31;
    const int gid = lane >> 2, tig = lane & 3;
    const int warp_m = wid / WARPS_N, warp_n = wid % WARPS_N;
    const int wm = warp_m * WM, wn = warp_n * WN;

    float acc[MT][NT_][4];
#pragma unroll
    for (int i = 0; i < MT; i++)
#pragma unroll
        for (int j = 0; j < NT_; j++)
#pragma unroll
            for (int q = 0; q < 4; q++) acc[i][j][q] = 0.f;

    auto load_stage = [&](int s, int k0) {
#pragma unroll
        for (int i = 0; i < (BM * 4) / NTHREADS; i++) {
            int id = tid + i * NTHREADS;
            int m = id >> 2, kc = (id & 3) * 4;
            cp16(&Asm[s][m][kc], A + (size_t)(bm + m) * K + k0 + kc);
        }
#pragma unroll
        for (int i = 0; i < (KT * BN / 4) / NTHREADS; i++) {
            int id = tid + i * NTHREADS;
            int kr = id / (BN / 4), nq = (id % (BN / 4)) * 4;
            cp16(&Bsm[s][kr][nq], B + (size_t)(k0 + kr) * N + bn + nq);
        }
    };

    const int nk = K / KT;      // >= 4 for all our shapes
    load_stage(0, 0); cp_commit();
    load_stage(1, KT); cp_commit();

    int s = 0;
    for (int kt = 0; kt < nk; kt++) {
        cp_wait1();            // stage kt data has arrived
        __syncthreads();       // visible to all; everyone done with stage (kt+2)%3
        if (kt + 2 < nk) load_stage((kt + 2) % STG, (kt + 2) * KT);
        cp_commit();

#pragma unroll
        for (int kk = 0; kk < KT; kk += 8) {
            unsigned af[MT][4], bf[NT_][2];
#pragma unroll
            for (int mt = 0; mt < MT; mt++) {
                int rm = wm + mt * 16 + gid;
                af[mt][0] = Asm[s][rm][kk + tig];
                af[mt][1] = Asm[s][rm + 8][kk + tig];
                af[mt][2] = Asm[s][rm][kk + tig + 4];
                af[mt][3] = Asm[s][rm + 8][kk + tig + 4];
            }
#pragma unroll
            for (int nt = 0; nt < NT_; nt++) {
                int cn = wn + nt * 8 + gid;
                bf[nt][0] = Bsm[s][kk + tig][cn];
                bf[nt][1] = Bsm[s][kk + tig + 4][cn];
            }
#pragma unroll
            for (int mt = 0; mt < MT; mt++)
#pragma unroll
                for (int nt = 0; nt < NT_; nt++)
                    mma_tf32(acc[mt][nt], af[mt], bf[nt]);
        }
        s = (s + 1 == STG) ? 0 : s + 1;
    }

#pragma unroll
    for (int mt = 0; mt < MT; mt++) {
#pragma unroll
        for (int nt = 0; nt < NT_; nt++) {
            int r0 = bm + wm + mt * 16 + gid;
            int c = bn + wn + nt * 8 + tig * 2;
            float v0 = acc[mt][nt][0], v1 = acc[mt][nt][1];
            float v2 = acc[mt][nt][2], v3 = acc[mt][nt][3];
            if (act == 1) {
                v0 = tanhf(v0); v1 = tanhf(v1); v2 = tanhf(v2); v3 = tanhf(v3);
            } else if (act == 2) {
                v0 = 1.f / (1.f + expf(-v0)); v1 = 1.f / (1.f + expf(-v1));
                v2 = 1.f / (1.f + expf(-v2)); v3 = 1.f / (1.f + expf(-v3));
            }
            if (rd) {
                v0 = rnd_tf32(v0); v1 = rnd_tf32(v1);
                v2 = rnd_tf32(v2); v3 = rnd_tf32(v3);
            }
            *(float2*)(C + (size_t)r0 * N + c) = make_float2(v0, v1);
            *(float2*)(C + (size_t)(r0 + 8) * N + c) = make_float2(v2, v3);
        }
    }
}

// ------------------------- token shift + 6 mixes (float4, tf32-rounded out) --------
__global__ void mix_kernel(const float4* __restrict__ x,
                           const float4* __restrict__ cr, const float4* __restrict__ cw,
                           const float4* __restrict__ ck, const float4* __restrict__ cv,
                           const float4* __restrict__ ca, const float4* __restrict__ cg) {
    size_t i = (size_t)blockIdx.x * blockDim.x + threadIdx.x;
    constexpr size_t TOT = (size_t)BTn * Cn / 4;
    constexpr int C4 = Cn / 4;
    if (i >= TOT) return;
    int c = (int)(i % C4);
    size_t bt = i / C4;
    int t = (int)(bt % Tn);
    float4 xc = x[i];
    float4 prev = (t == 0) ? make_float4(0.f, 0.f, 0.f, 0.f) : x[i - C4];
    float4 dx = make_float4(prev.x - xc.x, prev.y - xc.y, prev.z - xc.z, prev.w - xc.w);
#define MIXO(dst, coef) { \
    float4 cc = coef[c]; \
    ((float4*)dst)[i] = make_float4( \
        rnd_tf32(fmaf(dx.x, cc.x, xc.x)), rnd_tf32(fmaf(dx.y, cc.y, xc.y)), \
        rnd_tf32(fmaf(dx.z, cc.z, xc.z)), rnd_tf32(fmaf(dx.w, cc.w, xc.w))); }
    MIXO(g_xr, cr); MIXO(g_xw, cw); MIXO(g_xk, ck);
    MIXO(g_xv, cv); MIXO(g_xa, ca); MIXO(g_xg, cg);
#undef MIXO
}

// ------------------------- per-head elementwise stage 2 (warp per head) -----------
__global__ void __launch_bounds__(256) ew2_kernel(
        const float* __restrict__ w0, const float* __restrict__ a0,
        const float* __restrict__ v0, const float* __restrict__ kkw,
        const float* __restrict__ kaw, const float* __restrict__ vfirst) {
    int w = blockIdx.x * 8 + (threadIdx.x >> 5);
    int lane = threadIdx.x & 31;
    int bt = w / Hn, h = w % Hn;
    int b = bt / Tn, t = bt % Tn;
    size_t pb = ((size_t)(b * Hn + h) * Tn + t) * 384;
    size_t base = (size_t)bt * Cn + h * Nn;

    float kraw[2], kkp[2], av[2], vv[2], wv[2];
#pragma unroll
    for (int j = 0; j < 2; j++) {
        int n = lane + 32 * j;
        int c = h * Nn + n;
        size_t idx = base + n;
        kraw[j] = g_k[idx];
        kkp[j] = kraw[j] * kkw[c];
        av[j] = 1.f / (1.f + expf(-(a0[c] + g_za[idx])));
        float xw = -(w0[c] + g_w[idx]);
        float sp = (xw > 20.f) ? xw : log1pf(expf(xw));
        wv[j] = expf(-expf(-0.5f - sp));
        float vs = 1.f / (1.f + expf(-(v0[c] + g_zv[idx])));
        float vraw = g_v[idx];
        vv[j] = vraw + (vfirst[idx] - vraw) * vs;
    }
    float nrm2 = warp_sum(kkp[0] * kkp[0] + kkp[1] * kkp[1]);
    float inv = 1.f / fmaxf(sqrtf(nrm2), 1e-12f);

#pragma unroll
    for (int j = 0; j < 2; j++) {
        int n = lane + 32 * j;
        int c = h * Nn + n;
        size_t idx = base + n;
        float kkn = kkp[j] * inv;
        g_pack[pb +       n] = g_r[idx];
        g_pack[pb +  64 + n] = wv[j];
        g_pack[pb + 128 + n] = kraw[j] * (1.f + (av[j] - 1.f) * kaw[c]);
        g_pack[pb + 192 + n] = vv[j];
        g_pack[pb + 256 + n] = -kkn;
        g_pack[pb + 320 + n] = kkn * av[j];
    }
}

// ------------------------- WKV7 scan: 4-step groups, cp.async prefetch ------------
__global__ void __launch_bounds__(128) wkv7_scan() {
    const int bh = blockIdx.x >> 1;
    const int vh = blockIdx.x & 1;
    const int b = bh / Hn, h = bh % Hn;
    const int tid = threadIdx.x;
    const int v_local = tid >> 2;
    const int kq = tid & 3;
    const int v = vh * 32 + v_local;

    float S[16];
#pragma unroll
    for (int i = 0; i < 16; i++) S[i] = 0.f;

    __shared__ float4 sm4[2][4][96];
    const float4* pk4 = (const float4*)(g_pack + (size_t)bh * Tn * 384);
    size_t ybase = (size_t)b * Tn * Cn + (size_t)h * Nn + v;

    auto load_group = [&](int buf, int g) {
#pragma unroll
        for (int i = 0; i < 3; i++) {
            int id = tid + i * 128;
            int st = id / 96, off = id % 96;
            cp16(&sm4[buf][st][off], pk4 + (size_t)(g * 4 + st) * 96 + off);
        }
    };

    load_group(0, 0); cp_commit();
    load_group(1, 1); cp_commit();

    const int kb4 = kq * 4;
    constexpr int NG = Tn / 4;

    for (int g = 0; g < NG; g++) {
        cp_wait1();
        __syncthreads();
        const int buf = g & 1;

#pragma unroll
        for (int st = 0; st < 4; st++) {
            const float4* r4  = &sm4[buf][st][0  + kb4];
            const float4* w4  = &sm4[buf][st][16 + kb4];
            const float4* k4  = &sm4[buf][st][32 + kb4];
            const float4* ah4 = &sm4[buf][st][64 + kb4];
            const float4* bh4 = &sm4[buf][st][80 + kb4];
            const float vv = ((const float*)&sm4[buf][st][48])[v];

            float4 A0 = ah4[0], A1 = ah4[1], A2 = ah4[2], A3 = ah4[3];
            float sa0 = S[0] * A0.x, sa1 = S[4] * A1.x, sa2 = S[8] * A2.x, sa3 = S[12] * A3.x;
            sa0 = fmaf(S[1], A0.y, sa0); sa1 = fmaf(S[5], A1.y, sa1);
            sa2 = fmaf(S[9], A2.y, sa2); sa3 = fmaf(S[13], A3.y, sa3);
            sa0 = fmaf(S[2], A0.z, sa0); sa1 = fmaf(S[6], A1.z, sa1);
            sa2 = fmaf(S[10], A2.z, sa2); sa3 = fmaf(S[14], A3.z, sa3);
            sa0 = fmaf(S[3], A0.w, sa0); sa1 = fmaf(S[7], A1.w, sa1);
            sa2 = fmaf(S[11], A2.w, sa2); sa3 = fmaf(S[15], A3.w, sa3);
            float sa = (sa0 + sa1) + (sa2 + sa3);
            sa += __shfl_xor_sync(0xffffffffu, sa, 1);
            sa += __shfl_xor_sync(0xffffffffu, sa, 2);

            float y0 = 0.f, y1 = 0.f, y2 = 0.f, y3 = 0.f;
#pragma unroll
            for (int j = 0; j < 4; j++) {
                float4 W = w4[j], Bv = bh4[j], Kv = k4[j], R = r4[j];
                S[j*4+0] = fmaf(S[j*4+0], W.x, fmaf(sa, Bv.x, vv * Kv.x));
                S[j*4+1] = fmaf(S[j*4+1], W.y, fmaf(sa, Bv.y, vv * Kv.y));
                S[j*4+2] = fmaf(S[j*4+2], W.z, fmaf(sa, Bv.z, vv * Kv.z));
                S[j*4+3] = fmaf(S[j*4+3], W.w, fmaf(sa, Bv.w, vv * Kv.w));
                y0 = fmaf(S[j*4+0], R.x, y0);
                y1 = fmaf(S[j*4+1], R.y, y1);
                y2 = fmaf(S[j*4+2], R.z, y2);
                y3 = fmaf(S[j*4+3], R.w, y3);
            }
            float y = (y0 + y1) + (y2 + y3);
            y += __shfl_xor_sync(0xffffffffu, y, 1);
            y += __shfl_xor_sync(0xffffffffu, y, 2);
            if (kq == 0) g_y[ybase + (size_t)(g * 4 + st) * Cn] = y;
        }

        __syncthreads();
        if (g + 2 < NG) load_group(buf, g + 2);
        cp_commit();
    }
}

// ------------------------- groupnorm + rk residual + gate (warp per head) ---------
__global__ void __launch_bounds__(256) gn_kernel(
        const float* __restrict__ r_k, const float* __restrict__ gnw,
        const float* __restrict__ gnb) {
    int w = blockIdx.x * 8 + (threadIdx.x >> 5);
    int lane = threadIdx.x & 31;
    int bt = w / Hn, h = w % Hn;
    int b = bt / Tn, t = bt % Tn;
    size_t pb = ((size_t)(b * Hn + h) * Tn + t) * 384;
    size_t base = (size_t)bt * Cn + h * Nn;

    float yv[2], rr[2], kk[2], vv[2];
#pragma unroll
    for (int j = 0; j < 2; j++) {
        int n = lane + 32 * j;
        yv[j] = g_y[base + n];
        rr[j] = g_pack[pb + n];
        kk[j] = g_pack[pb + 128 + n];
        vv[j] = g_pack[pb + 192 + n];
    }
    float mu = warp_sum(yv[0] + yv[1]) * (1.f / 64.f);
    float d0 = yv[0] - mu, d1 = yv[1] - mu;
    float var = warp_sum(d0 * d0 + d1 * d1) * (1.f / 64.f);
    float rs = rsqrtf(var + (float)(Nn * 1e-5));

    float dp0, dp1;
    {
        int c0 = h * Nn + lane, c1 = c0 + 32;
        dp0 = rr[0] * kk[0] * r_k[c0];
        dp1 = rr[1] * kk[1] * r_k[c1];
    }
    float dot = warp_sum(dp0 + dp1);

#pragma unroll
    for (int j = 0; j < 2; j++) {
        int n = lane + 32 * j;
        int c = h * Nn + n;
        size_t idx = base + n;
        float d = (j == 0) ? d0 : d1;
        float yn = d * rs * gnw[c] + gnb[c];
        g_op[idx] = rnd_tf32((yn + dot * vv[j]) * g_g[idx]);
    }
}

// ------------------------- launch -------------------------
extern "C" void kernel_launch(void* const* d_in, const int* in_sizes, int n_in,
                              void* d_out, int out_size) {
    (void)in_sizes; (void)n_in; (void)out_size;
    const float* x      = (const float*)d_in[0];
    const float* vfirst = (const float*)d_in[1];
    const float* x_r = (const float*)d_in[2];
    const float* x_w = (const float*)d_in[3];
    const float* x_k = (const float*)d_in[4];
    const float* x_v = (const float*)d_in[5];
    const float* x_a = (const float*)d_in[6];
    const float* x_g = (const float*)d_in[7];
    const float* w0  = (const float*)d_in[8];
    const float* w1  = (const float*)d_in[9];
    const float* w2  = (const float*)d_in[10];
    const float* a0  = (const float*)d_in[11];
    const float* a1  = (const float*)d_in[12];
    const float* a2  = (const float*)d_in[13];
    const float* v0  = (const float*)d_in[14];
    const float* v1  = (const float*)d_in[15];
    const float* v2  = (const float*)d_in[16];
    const float* g1  = (const float*)d_in[17];
    const float* g2  = (const float*)d_in[18];
    const float* k_k = (const float*)d_in[19];
    const float* k_a = (const float*)d_in[20];
    const float* r_k = (const float*)d_in[21];
    const float* W_r = (const float*)d_in[22];
    const float* W_k = (const float*)d_in[23];
    const float* W_v = (const float*)d_in[24];
    const float* W_o = (const float*)d_in[25];
    const float* gnw = (const float*)d_in[26];
    const float* gnb = (const float*)d_in[27];
    float* out = (float*)d_out;

#define GETP(name, sym) float* name; cudaGetSymbolAddress((void**)&name, sym)
    GETP(p_xr, g_xr); GETP(p_xw, g_xw); GETP(p_xk, g_xk); GETP(p_xv, g_xv);
    GETP(p_xa, g_xa); GETP(p_xg, g_xg);
    GETP(p_r, g_r); GETP(p_k, g_k); GETP(p_v, g_v); GETP(p_w, g_w);
    GETP(p_za, g_za); GETP(p_zv, g_zv); GETP(p_g, g_g); GETP(p_op, g_op);
    GETP(p_tw, g_tw); GETP(p_ta, g_ta); GETP(p_tv, g_tv); GETP(p_tg, g_tg);
    GETP(p_Wr, g_Wr); GETP(p_Wk, g_Wk); GETP(p_Wv, g_Wv); GETP(p_Wo, g_Wo);
    GETP(p_w1, g_w1r); GETP(p_a1, g_a1r); GETP(p_v1, g_v1r); GETP(p_g1, g_g1r);
    GETP(p_w2, g_w2r); GETP(p_a2, g_a2r); GETP(p_v2, g_v2r); GETP(p_g2, g_g2r);
#undef GETP

    // 0) weight rounding prepass (12 buffers over grid.y)
    {
        RP rp = {};
        const float* srcs[12] = {W_r, W_k, W_v, W_o, w1, a1, v1, g1, w2, a2, v2, g2};
        float* dsts[12] = {p_Wr, p_Wk, p_Wv, p_Wo, p_w1, p_a1, p_v1, p_g1,
                           p_w2, p_a2, p_v2, p_g2};
        int cnt[12] = {Cn*Cn, Cn*Cn, Cn*Cn, Cn*Cn, Cn*96, Cn*96, Cn*64, Cn*256,
                       96*Cn, 96*Cn, 64*Cn, 256*Cn};
        int maxn4 = 0;
        for (int i = 0; i < 12; i++) {
            rp.src[i] = (const float4*)srcs[i];
            rp.dst[i] = (float4*)dsts[i];
            rp.n4[i] = cnt[i] / 4;
            if (rp.n4[i] > maxn4) maxn4 = rp.n4[i];
        }
        round_weights<<<dim3((maxn4 + 255) / 256, 12), 256>>>(rp);
    }

    // 1) token shift + mixes (outputs tf32-rounded)
    mix_kernel<<<(BTn * Cn / 4 + 255) / 256, 256>>>(
        (const float4*)x, (const float4*)x_r, (const float4*)x_w, (const float4*)x_k,
        (const float4*)x_v, (const float4*)x_a, (const float4*)x_g);

    constexpr int KT = 16, STG = 3;
    const int smemA = STG * 128 * (KT + 4) * 4 + STG * KT * (128 + 8) * 4;   // 56832
    const int smemB = STG * 64 * (KT + 4) * 4 + STG * KT * (32 + 8) * 4;     // 23040
    cudaFuncSetAttribute(gemm3<128, 128, 64, 32>,
                         cudaFuncAttributeMaxDynamicSharedMemorySize, smemA);
    cudaFuncSetAttribute(gemm3<64, 32, 32, 16>,
                         cudaFuncAttributeMaxDynamicSharedMemorySize, smemB);

    // 2) r/k/v projections
    {
        GB p = {};
        p.A[0] = p_xr; p.A[1] = p_xk; p.A[2] = p_xv;
        p.Bw[0] = p_Wr; p.Bw[1] = p_Wk; p.Bw[2] = p_Wv;
        p.C[0] = p_r;  p.C[1] = p_k;  p.C[2] = p_v;
        for (int z = 0; z < 3; z++) { p.N[z] = Cn; p.K[z] = Cn; p.act[z] = 0; p.rnd[z] = 0; }
        gemm3<128, 128, 64, 32><<<dim3(16, 16, 3), 256, smemA>>>(p);
    }

    // 3a) LoRA ups (outputs rounded — they feed the down GEMMs)
    {
        GB p = {};
        p.A[0] = p_xw; p.A[1] = p_xa; p.A[2] = p_xv; p.A[3] = p_xg;
        p.Bw[0] = p_w1; p.Bw[1] = p_a1; p.Bw[2] = p_v1; p.Bw[3] = p_g1;
        p.C[0] = p_tw; p.C[1] = p_ta; p.C[2] = p_tv; p.C[3] = p_tg;
        p.N[0] = 96; p.N[1] = 96; p.N[2] = 64; p.N[3] = 256;
        for (int z = 0; z < 4; z++) { p.K[z] = Cn; p.rnd[z] = 1; }
        p.act[0] = 1; p.act[1] = 0; p.act[2] = 0; p.act[3] = 2;
        gemm3<64, 32, 32, 16><<<dim3(8, BTn / 64, 4), 128, smemB>>>(p);
    }

    // 3b) LoRA downs
    {
        GB p = {};
        p.A[0] = p_tw; p.A[1] = p_ta; p.A[2] = p_tv; p.A[3] = p_tg;
        p.Bw[0] = p_w2; p.Bw[1] = p_a2; p.Bw[2] = p_v2; p.Bw[3] = p_g2;
        p.C[0] = p_w;  p.C[1] = p_za; p.C[2] = p_zv; p.C[3] = p_g;
        p.K[0] = 96; p.K[1] = 96; p.K[2] = 64; p.K[3] = 256;
        for (int z = 0; z < 4; z++) { p.N[z] = Cn; p.act[z] = 0; p.rnd[z] = 0; }
        gemm3<128, 128, 64, 32><<<dim3(16, 16, 4), 256, smemA>>>(p);
    }

    // 4) per-head elementwise -> packed scan operands
    ew2_kernel<<<BTn * Hn / 8, 256>>>(w0, a0, v0, k_k, k_a, vfirst);

    // 5) WKV7 scan
    wkv7_scan<<<2 * Bn * Hn, 128>>>();

    // 6) groupnorm + residual + gate (output rounded — feeds out-proj)
    gn_kernel<<<BTn * Hn / 8, 256>>>(r_k, gnw, gnb);

    // 7) output projection
    {
        GB p = {};
        p.A[0] = p_op; p.Bw[0] = p_Wo; p.C[0] = out;
        p.N[0] = Cn; p.K[0] = Cn; p.act[0] = 0; p.rnd[0] = 0;
        gemm3<128, 128, 64, 32><<<dim3(16, 16, 1), 256, smemA>>>(p);
    }
}

// round 7
// speedup vs baseline: 4.7910x; 1.0153x over previous
#include <cuda_runtime.h>
#include <math.h>

// Problem constants
#define Bn 2
#define Tn 1024
#define Cn 2048
#define Hn 32
#define Nn 64
#define BTn (Bn*Tn)

// ------------------------- scratch (static device globals) -------------------------
__device__ float g_xr[BTn*Cn];
__device__ float g_xw[BTn*Cn];
__device__ float g_xk[BTn*Cn];
__device__ float g_xv[BTn*Cn];
__device__ float g_xa[BTn*Cn];
__device__ float g_xg[BTn*Cn];
__device__ float g_r [BTn*Cn];
__device__ float g_k [BTn*Cn];
__device__ float g_v [BTn*Cn];
__device__ float g_w [BTn*Cn];
__device__ float g_za[BTn*Cn];
__device__ float g_zv[BTn*Cn];
__device__ float g_g [BTn*Cn];
__device__ float g_y [BTn*Cn];
__device__ float g_op[BTn*Cn];
__device__ float g_tw[BTn*128];   // padded 96->128
__device__ float g_ta[BTn*128];   // padded 96->128
__device__ float g_tv[BTn*64];
__device__ float g_tg[BTn*256];
// packed scan operands: [B*H][T][6*64]  order: r,w,k,v,ah,bh
__device__ float g_pack[(size_t)Bn*Hn*Tn*384];
// pre-rounded (tf32) weights
__device__ float g_Wr[Cn*Cn];
__device__ float g_Wk[Cn*Cn];
__device__ float g_Wv[Cn*Cn];
__device__ float g_Wo[Cn*Cn];
__device__ float g_w1r[Cn*128];   // padded cols 96->128 (zeros)
__device__ float g_a1r[Cn*128];   // padded cols 96->128 (zeros)
__device__ float g_v1r[Cn*64];
__device__ float g_g1r[Cn*256];
__device__ float g_w2r[128*Cn];   // padded rows 96->128 (zeros)
__device__ float g_a2r[128*Cn];   // padded rows 96->128 (zeros)
__device__ float g_v2r[64*Cn];
__device__ float g_g2r[256*Cn];

// ------------------------- helpers -------------------------
__device__ __forceinline__ unsigned f2tf32(float f) {
    unsigned u;
    asm("cvt.rna.tf32.f32 %0, %1;" : "=r"(u) : "f"(f));
    return u;
}
__device__ __forceinline__ float rnd_tf32(float f) { return __uint_as_float(f2tf32(f)); }

__device__ __forceinline__ void mma_tf32(float* d, const unsigned* a, const unsigned* b) {
    asm volatile(
        "mma.sync.aligned.m16n8k8.row.col.f32.tf32.tf32.f32 "
        "{%0,%1,%2,%3}, {%4,%5,%6,%7}, {%8,%9}, {%0,%1,%2,%3};"
        : "+f"(d[0]), "+f"(d[1]), "+f"(d[2]), "+f"(d[3])
        : "r"(a[0]), "r"(a[1]), "r"(a[2]), "r"(a[3]),
          "r"(b[0]), "r"(b[1]));
}

__device__ __forceinline__ void cp16(void* smem, const void* g) {
    unsigned saddr = (unsigned)__cvta_generic_to_shared(smem);
    asm volatile("cp.async.cg.shared.global [%0], [%1], 16;" :: "r"(saddr), "l"(g));
}
__device__ __forceinline__ void cp_commit() { asm volatile("cp.async.commit_group;" ::: "memory"); }
__device__ __forceinline__ void cp_wait1()  { asm volatile("cp.async.wait_group 1;" ::: "memory"); }

__device__ __forceinline__ float warp_sum(float v) {
#pragma unroll
    for (int o = 16; o > 0; o >>= 1) v += __shfl_xor_sync(0xffffffffu, v, o);
    return v;
}

// ------------------------- weight rounding prepass -------------------------
struct RP {
    const float4* src[8];
    float4* dst[8];
    int n4[8];
};
__global__ void round_weights(RP p) {
    int zb = blockIdx.y;
    int i = blockIdx.x * blockDim.x + threadIdx.x;
    if (i >= p.n4[zb]) return;
    float4 v = p.src[zb][i];
    v.x = rnd_tf32(v.x); v.y = rnd_tf32(v.y);
    v.z = rnd_tf32(v.z); v.w = rnd_tf32(v.w);
    p.dst[zb][i] = v;
}

// padded rounding: dst [dstR][dstC], src [srcR][srcC]; zero outside
struct PP {
    const float* src[4];
    float* dst[4];
    int dstR[4], dstC[4], srcR[4], srcC[4];
};
__global__ void pad_weights(PP p) {
    int zb = blockIdx.y;
    int i = blockIdx.x * blockDim.x + threadIdx.x;
    int tot = p.dstR[zb] * p.dstC[zb];
    if (i >= tot) return;
    int r = i / p.dstC[zb], c = i % p.dstC[zb];
    float v = 0.f;
    if (r < p.srcR[zb] && c < p.srcC[zb])
        v = rnd_tf32(p.src[zb][r * p.srcC[zb] + c]);
    p.dst[zb][i] = v;
}

// ------------------------- batched 3-stage tf32 GEMM (pre-rounded operands) --------
struct GB {
    const float* A[4];
    const float* Bw[4];
    float*       C[4];
    int N[4];
    int K[4];
    int act[4];   // 0=none 1=tanh 2=sigmoid
    int rnd[4];   // round output to tf32?
};

template<int BM, int BN, int WM, int WN>
__global__ void __launch_bounds__((BM/WM)*(BN/WN)*32)
gemm3(GB p) {
    constexpr int KT = 16;
    constexpr int STG = 3;
    constexpr int WARPS_M = BM / WM;
    constexpr int WARPS_N = BN / WN;
    constexpr int NTHREADS = WARPS_M * WARPS_N * 32;
    constexpr int MT = WM / 16;
    constexpr int NT_ = WN / 8;
    constexpr int ASTR = KT + 4;
    constexpr int BSTR = BN + 8;

    extern __shared__ unsigned dsm[];
    unsigned (*Asm)[BM][ASTR] = (unsigned(*)[BM][ASTR])dsm;
    unsigned (*Bsm)[KT][BSTR] = (unsigned(*)[KT][BSTR])(dsm + STG * BM * ASTR);

    const int z = blockIdx.z;
    const float* A = p.A[z];
    const float* B = p.Bw[z];
    float* C = p.C[z];
    const int N = p.N[z], K = p.K[z], act = p.act[z], rd = p.rnd[z];
    const int bn = blockIdx.x * BN;
    if (bn >= N) return;
    const int bm = blockIdx.y * BM;

    const int tid = threadIdx.x;
    const int wid = tid >> 5, lane = tid & 31;
    const int gid = lane >> 2, tig = lane & 3;
    const int warp_m = wid / WARPS_N, warp_n = wid % WARPS_N;
    const int wm = warp_m * WM, wn = warp_n * WN;

    float acc[MT][NT_][4];
#pragma unroll
    for (int i = 0; i < MT; i++)
#pragma unroll
        for (int j = 0; j < NT_; j++)
#pragma unroll
            for (int q = 0; q < 4; q++) acc[i][j][q] = 0.f;

    auto load_stage = [&](int s, int k0) {
#pragma unroll
        for (int i = 0; i < (BM * 4) / NTHREADS; i++) {
            int id = tid + i * NTHREADS;
            int m = id >> 2, kc = (id & 3) * 4;
            cp16(&Asm[s][m][kc], A + (size_t)(bm + m) * K + k0 + kc);
        }
#pragma unroll
        for (int i = 0; i < (KT * BN / 4) / NTHREADS; i++) {
            int id = tid + i * NTHREADS;
            int kr = id / (BN / 4), nq = (id % (BN / 4)) * 4;
            cp16(&Bsm[s][kr][nq], B + (size_t)(k0 + kr) * N + bn + nq);
        }
    };

    const int nk = K / KT;
    load_stage(0, 0); cp_commit();
    load_stage(1, KT); cp_commit();

    int s = 0;
    for (int kt = 0; kt < nk; kt++) {
        cp_wait1();
        __syncthreads();
        if (kt + 2 < nk) load_stage((kt + 2) % STG, (kt + 2) * KT);
        cp_commit();

#pragma unroll
        for (int kk = 0; kk < KT; kk += 8) {
            unsigned af[MT][4], bf[NT_][2];
#pragma unroll
            for (int mt = 0; mt < MT; mt++) {
                int rm = wm + mt * 16 + gid;
                af[mt][0] = Asm[s][rm][kk + tig];
                af[mt][1] = Asm[s][rm + 8][kk + tig];
                af[mt][2] = Asm[s][rm][kk + tig + 4];
                af[mt][3] = Asm[s][rm + 8][kk + tig + 4];
            }
#pragma unroll
            for (int nt = 0; nt < NT_; nt++) {
                int cn = wn + nt * 8 + gid;
                bf[nt][0] = Bsm[s][kk + tig][cn];
                bf[nt][1] = Bsm[s][kk + tig + 4][cn];
            }
#pragma unroll
            for (int mt = 0; mt < MT; mt++)
#pragma unroll
                for (int nt = 0; nt < NT_; nt++)
                    mma_tf32(acc[mt][nt], af[mt], bf[nt]);
        }
        s = (s + 1 == STG) ? 0 : s + 1;
    }

#pragma unroll
    for (int mt = 0; mt < MT; mt++) {
#pragma unroll
        for (int nt = 0; nt < NT_; nt++) {
            int r0 = bm + wm + mt * 16 + gid;
            int c = bn + wn + nt * 8 + tig * 2;
            float v0 = acc[mt][nt][0], v1 = acc[mt][nt][1];
            float v2 = acc[mt][nt][2], v3 = acc[mt][nt][3];
            if (act == 1) {
                v0 = tanhf(v0); v1 = tanhf(v1); v2 = tanhf(v2); v3 = tanhf(v3);
            } else if (act == 2) {
                v0 = 1.f / (1.f + expf(-v0)); v1 = 1.f / (1.f + expf(-v1));
                v2 = 1.f / (1.f + expf(-v2)); v3 = 1.f / (1.f + expf(-v3));
            }
            if (rd) {
                v0 = rnd_tf32(v0); v1 = rnd_tf32(v1);
                v2 = rnd_tf32(v2); v3 = rnd_tf32(v3);
            }
            *(float2*)(C + (size_t)r0 * N + c) = make_float2(v0, v1);
            *(float2*)(C + (size_t)(r0 + 8) * N + c) = make_float2(v2, v3);
        }
    }
}

// ------------------------- token shift + 6 mixes (float4, tf32-rounded out) --------
__global__ void mix_kernel(const float4* __restrict__ x,
                           const float4* __restrict__ cr, const float4* __restrict__ cw,
                           const float4* __restrict__ ck, const float4* __restrict__ cv,
                           const float4* __restrict__ ca, const float4* __restrict__ cg) {
    size_t i = (size_t)blockIdx.x * blockDim.x + threadIdx.x;
    constexpr size_t TOT = (size_t)BTn * Cn / 4;
    constexpr int C4 = Cn / 4;
    if (i >= TOT) return;
    int c = (int)(i % C4);
    size_t bt = i / C4;
    int t = (int)(bt % Tn);
    float4 xc = x[i];
    float4 prev = (t == 0) ? make_float4(0.f, 0.f, 0.f, 0.f) : x[i - C4];
    float4 dx = make_float4(prev.x - xc.x, prev.y - xc.y, prev.z - xc.z, prev.w - xc.w);
#define MIXO(dst, coef) { \
    float4 cc = coef[c]; \
    ((float4*)dst)[i] = make_float4( \
        rnd_tf32(fmaf(dx.x, cc.x, xc.x)), rnd_tf32(fmaf(dx.y, cc.y, xc.y)), \
        rnd_tf32(fmaf(dx.z, cc.z, xc.z)), rnd_tf32(fmaf(dx.w, cc.w, xc.w))); }
    MIXO(g_xr, cr); MIXO(g_xw, cw); MIXO(g_xk, ck);
    MIXO(g_xv, cv); MIXO(g_xa, ca); MIXO(g_xg, cg);
#undef MIXO
}

// ------------------------- per-head elementwise stage 2 (warp per head) -----------
__global__ void __launch_bounds__(256) ew2_kernel(
        const float* __restrict__ w0, const float* __restrict__ a0,
        const float* __restrict__ v0, const float* __restrict__ kkw,
        const float* __restrict__ kaw, const float* __restrict__ vfirst) {
    int w = blockIdx.x * 8 + (threadIdx.x >> 5);
    int lane = threadIdx.x & 31;
    int bt = w / Hn, h = w % Hn;
    int b = bt / Tn, t = bt % Tn;
    size_t pb = ((size_t)(b * Hn + h) * Tn + t) * 384;
    size_t base = (size_t)bt * Cn + h * Nn;

    float kraw[2], kkp[2], av[2], vv[2], wv[2];
#pragma unroll
    for (int j = 0; j < 2; j++) {
        int n = lane + 32 * j;
        int c = h * Nn + n;
        size_t idx = base + n;
        kraw[j] = g_k[idx];
        kkp[j] = kraw[j] * kkw[c];
        av[j] = 1.f / (1.f + expf(-(a0[c] + g_za[idx])));
        float xw = -(w0[c] + g_w[idx]);
        float sp = (xw > 20.f) ? xw : log1pf(expf(xw));
        wv[j] = expf(-expf(-0.5f - sp));
        float vs = 1.f / (1.f + expf(-(v0[c] + g_zv[idx])));
        float vraw = g_v[idx];
        vv[j] = vraw + (vfirst[idx] - vraw) * vs;
    }
    float nrm2 = warp_sum(kkp[0] * kkp[0] + kkp[1] * kkp[1]);
    float inv = 1.f / fmaxf(sqrtf(nrm2), 1e-12f);

#pragma unroll
    for (int j = 0; j < 2; j++) {
        int n = lane + 32 * j;
        int c = h * Nn + n;
        size_t idx = base + n;
        float kkn = kkp[j] * inv;
        g_pack[pb +       n] = g_r[idx];
        g_pack[pb +  64 + n] = wv[j];
        g_pack[pb + 128 + n] = kraw[j] * (1.f + (av[j] - 1.f) * kaw[c]);
        g_pack[pb + 192 + n] = vv[j];
        g_pack[pb + 256 + n] = -kkn;
        g_pack[pb + 320 + n] = kkn * av[j];
    }
}

// ------------------------- WKV7 scan: 8-step groups, cp.async prefetch ------------
__global__ void __launch_bounds__(128) wkv7_scan() {
    const int bh = blockIdx.x >> 1;
    const int vh = blockIdx.x & 1;
    const int b = bh / Hn, h = bh % Hn;
    const int tid = threadIdx.x;
    const int v_local = tid >> 2;
    const int kq = tid & 3;
    const int v = vh * 32 + v_local;
    constexpr int GS = 8;                  // steps per group

    float S[16];
#pragma unroll
    for (int i = 0; i < 16; i++) S[i] = 0.f;

    __shared__ float4 sm4[2][GS][96];
    const float4* pk4 = (const float4*)(g_pack + (size_t)bh * Tn * 384);
    size_t ybase = (size_t)b * Tn * Cn + (size_t)h * Nn + v;

    auto load_group = [&](int buf, int g) {
#pragma unroll
        for (int i = 0; i < (GS * 96) / 128; i++) {
            int id = tid + i * 128;
            int st = id / 96, off = id % 96;
            cp16(&sm4[buf][st][off], pk4 + (size_t)(g * GS + st) * 96 + off);
        }
    };

    load_group(0, 0); cp_commit();
    load_group(1, 1); cp_commit();

    const int kb4 = kq * 4;
    constexpr int NG = Tn / GS;

    for (int g = 0; g < NG; g++) {
        cp_wait1();
        __syncthreads();
        const int buf = g & 1;

#pragma unroll
        for (int st = 0; st < GS; st++) {
            const float4* r4  = &sm4[buf][st][0  + kb4];
            const float4* w4  = &sm4[buf][st][16 + kb4];
            const float4* k4  = &sm4[buf][st][32 + kb4];
            const float4* ah4 = &sm4[buf][st][64 + kb4];
            const float4* bh4 = &sm4[buf][st][80 + kb4];
            const float vv = ((const float*)&sm4[buf][st][48])[v];

            float4 A0 = ah4[0], A1 = ah4[1], A2 = ah4[2], A3 = ah4[3];
            float sa0 = S[0] * A0.x, sa1 = S[4] * A1.x, sa2 = S[8] * A2.x, sa3 = S[12] * A3.x;
            sa0 = fmaf(S[1], A0.y, sa0); sa1 = fmaf(S[5], A1.y, sa1);
            sa2 = fmaf(S[9], A2.y, sa2); sa3 = fmaf(S[13], A3.y, sa3);
            sa0 = fmaf(S[2], A0.z, sa0); sa1 = fmaf(S[6], A1.z, sa1);
            sa2 = fmaf(S[10], A2.z, sa2); sa3 = fmaf(S[14], A3.z, sa3);
            sa0 = fmaf(S[3], A0.w, sa0); sa1 = fmaf(S[7], A1.w, sa1);
            sa2 = fmaf(S[11], A2.w, sa2); sa3 = fmaf(S[15], A3.w, sa3);
            float sa = (sa0 + sa1) + (sa2 + sa3);
            sa += __shfl_xor_sync(0xffffffffu, sa, 1);
            sa += __shfl_xor_sync(0xffffffffu, sa, 2);

            float y0 = 0.f, y1 = 0.f, y2 = 0.f, y3 = 0.f;
#pragma unroll
            for (int j = 0; j < 4; j++) {
                float4 W = w4[j], Bv = bh4[j], Kv = k4[j], R = r4[j];
                S[j*4+0] = fmaf(S[j*4+0], W.x, fmaf(sa, Bv.x, vv * Kv.x));
                S[j*4+1] = fmaf(S[j*4+1], W.y, fmaf(sa, Bv.y, vv * Kv.y));
                S[j*4+2] = fmaf(S[j*4+2], W.z, fmaf(sa, Bv.z, vv * Kv.z));
                S[j*4+3] = fmaf(S[j*4+3], W.w, fmaf(sa, Bv.w, vv * Kv.w));
                y0 = fmaf(S[j*4+0], R.x, y0);
                y1 = fmaf(S[j*4+1], R.y, y1);
                y2 = fmaf(S[j*4+2], R.z, y2);
                y3 = fmaf(S[j*4+3], R.w, y3);
            }
            float y = (y0 + y1) + (y2 + y3);
            y += __shfl_xor_sync(0xffffffffu, y, 1);
            y += __shfl_xor_sync(0xffffffffu, y, 2);
            if (kq == 0) g_y[ybase + (size_t)(g * GS + st) * Cn] = y;
        }

        __syncthreads();
        if (g + 2 < NG) load_group(buf, g + 2);
        cp_commit();
    }
}

// ------------------------- groupnorm + rk residual + gate (warp per head) ---------
__global__ void __launch_bounds__(256) gn_kernel(
        const float* __restrict__ r_k, const float* __restrict__ gnw,
        const float* __restrict__ gnb) {
    int w = blockIdx.x * 8 + (threadIdx.x >> 5);
    int lane = threadIdx.x & 31;
    int bt = w / Hn, h = w % Hn;
    int b = bt / Tn, t = bt % Tn;
    size_t pb = ((size_t)(b * Hn + h) * Tn + t) * 384;
    size_t base = (size_t)bt * Cn + h * Nn;

    float yv[2], rr[2], kk[2], vv[2];
#pragma unroll
    for (int j = 0; j < 2; j++) {
        int n = lane + 32 * j;
        yv[j] = g_y[base + n];
        rr[j] = g_pack[pb + n];
        kk[j] = g_pack[pb + 128 + n];
        vv[j] = g_pack[pb + 192 + n];
    }
    float mu = warp_sum(yv[0] + yv[1]) * (1.f / 64.f);
    float d0 = yv[0] - mu, d1 = yv[1] - mu;
    float var = warp_sum(d0 * d0 + d1 * d1) * (1.f / 64.f);
    float rs = rsqrtf(var + (float)(Nn * 1e-5));

    float dp0, dp1;
    {
        int c0 = h * Nn + lane, c1 = c0 + 32;
        dp0 = rr[0] * kk[0] * r_k[c0];
        dp1 = rr[1] * kk[1] * r_k[c1];
    }
    float dot = warp_sum(dp0 + dp1);

#pragma unroll
    for (int j = 0; j < 2; j++) {
        int n = lane + 32 * j;
        int c = h * Nn + n;
        size_t idx = base + n;
        float d = (j == 0) ? d0 : d1;
        float yn = d * rs * gnw[c] + gnb[c];
        g_op[idx] = rnd_tf32((yn + dot * vv[j]) * g_g[idx]);
    }
}

// ------------------------- launch -------------------------
extern "C" void kernel_launch(void* const* d_in, const int* in_sizes, int n_in,
                              void* d_out, int out_size) {
    (void)in_sizes; (void)n_in; (void)out_size;
    const float* x      = (const float*)d_in[0];
    const float* vfirst = (const float*)d_in[1];
    const float* x_r = (const float*)d_in[2];
    const float* x_w = (const float*)d_in[3];
    const float* x_k = (const float*)d_in[4];
    const float* x_v = (const float*)d_in[5];
    const float* x_a = (const float*)d_in[6];
    const float* x_g = (const float*)d_in[7];
    const float* w0  = (const float*)d_in[8];
    const float* w1  = (const float*)d_in[9];
    const float* w2  = (const float*)d_in[10];
    const float* a0  = (const float*)d_in[11];
    const float* a1  = (const float*)d_in[12];
    const float* a2  = (const float*)d_in[13];
    const float* v0  = (const float*)d_in[14];
    const float* v1  = (const float*)d_in[15];
    const float* v2  = (const float*)d_in[16];
    const float* g1  = (const float*)d_in[17];
    const float* g2  = (const float*)d_in[18];
    const float* k_k = (const float*)d_in[19];
    const float* k_a = (const float*)d_in[20];
    const float* r_k = (const float*)d_in[21];
    const float* W_r = (const float*)d_in[22];
    const float* W_k = (const float*)d_in[23];
    const float* W_v = (const float*)d_in[24];
    const float* W_o = (const float*)d_in[25];
    const float* gnw = (const float*)d_in[26];
    const float* gnb = (const float*)d_in[27];
    float* out = (float*)d_out;

#define GETP(name, sym) float* name; cudaGetSymbolAddress((void**)&name, sym)
    GETP(p_xr, g_xr); GETP(p_xw, g_xw); GETP(p_xk, g_xk); GETP(p_xv, g_xv);
    GETP(p_xa, g_xa); GETP(p_xg, g_xg);
    GETP(p_r, g_r); GETP(p_k, g_k); GETP(p_v, g_v); GETP(p_w, g_w);
    GETP(p_za, g_za); GETP(p_zv, g_zv); GETP(p_g, g_g); GETP(p_op, g_op);
    GETP(p_tw, g_tw); GETP(p_ta, g_ta); GETP(p_tv, g_tv); GETP(p_tg, g_tg);
    GETP(p_Wr, g_Wr); GETP(p_Wk, g_Wk); GETP(p_Wv, g_Wv); GETP(p_Wo, g_Wo);
    GETP(p_w1, g_w1r); GETP(p_a1, g_a1r); GETP(p_v1, g_v1r); GETP(p_g1, g_g1r);
    GETP(p_w2, g_w2r); GETP(p_a2, g_a2r); GETP(p_v2, g_v2r); GETP(p_g2, g_g2r);
#undef GETP

    // persistent side stream + events for fork/join under graph capture
    static cudaStream_t s1 = nullptr;
    static cudaEvent_t evFork = nullptr, evJoin = nullptr;
    if (!s1) {
        cudaStreamCreateWithFlags(&s1, cudaStreamNonBlocking);
        cudaEventCreateWithFlags(&evFork, cudaEventDisableTiming);
        cudaEventCreateWithFlags(&evJoin, cudaEventDisableTiming);
    }

    // 0) weight rounding prepass: 8 unpadded buffers (float4) + 4 padded (scalar)
    {
        RP rp = {};
        const float* srcs[8] = {W_r, W_k, W_v, W_o, v1, g1, v2, g2};
        float* dsts[8] = {p_Wr, p_Wk, p_Wv, p_Wo, p_v1, p_g1, p_v2, p_g2};
        int cnt[8] = {Cn*Cn, Cn*Cn, Cn*Cn, Cn*Cn, Cn*64, Cn*256, 64*Cn, 256*Cn};
        int maxn4 = 0;
        for (int i = 0; i < 8; i++) {
            rp.src[i] = (const float4*)srcs[i];
            rp.dst[i] = (float4*)dsts[i];
            rp.n4[i] = cnt[i] / 4;
            if (rp.n4[i] > maxn4) maxn4 = rp.n4[i];
        }
        round_weights<<<dim3((maxn4 + 255) / 256, 8), 256>>>(rp);

        PP pp = {};
        const float* psrc[4] = {w1, a1, w2, a2};
        float* pdst[4] = {p_w1, p_a1, p_w2, p_a2};
        // w1: [Cn,96]->[Cn,128]; a1 same; w2: [96,Cn]->[128,Cn]; a2 same
        int dR[4] = {Cn, Cn, 128, 128}, dC[4] = {128, 128, Cn, Cn};
        int sR[4] = {Cn, Cn, 96, 96},   sC[4] = {96, 96, Cn, Cn};
        int maxt = 0;
        for (int i = 0; i < 4; i++) {
            pp.src[i] = psrc[i]; pp.dst[i] = pdst[i];
            pp.dstR[i] = dR[i]; pp.dstC[i] = dC[i];
            pp.srcR[i] = sR[i]; pp.srcC[i] = sC[i];
            if (dR[i] * dC[i] > maxt) maxt = dR[i] * dC[i];
        }
        pad_weights<<<dim3((maxt + 255) / 256, 4), 256>>>(pp);
    }

    // 1) token shift + mixes (outputs tf32-rounded)
    mix_kernel<<<(BTn * Cn / 4 + 255) / 256, 256>>>(
        (const float4*)x, (const float4*)x_r, (const float4*)x_w, (const float4*)x_k,
        (const float4*)x_v, (const float4*)x_a, (const float4*)x_g);

    constexpr int KT = 16, STG = 3;
    const int smemA  = STG * (128 * (KT + 4) + KT * (128 + 8)) * 4;   // 56832
    const int smemUp = STG * (128 * (KT + 4) + KT * (64 + 8)) * 4;    // 44544
    cudaFuncSetAttribute(gemm3<128, 128, 64, 32>,
                         cudaFuncAttributeMaxDynamicSharedMemorySize, smemA);
    cudaFuncSetAttribute(gemm3<128, 64, 64, 32>,
                         cudaFuncAttributeMaxDynamicSharedMemorySize, smemUp);

    // fork: side stream runs the LoRA chain concurrently with r/k/v
    cudaEventRecord(evFork, 0);
    cudaStreamWaitEvent(s1, evFork, 0);

    // 2) r/k/v projections (main stream)
    {
        GB p = {};
        p.A[0] = p_xr; p.A[1] = p_xk; p.A[2] = p_xv;
        p.Bw[0] = p_Wr; p.Bw[1] = p_Wk; p.Bw[2] = p_Wv;
        p.C[0] = p_r;  p.C[1] = p_k;  p.C[2] = p_v;
        for (int z = 0; z < 3; z++) { p.N[z] = Cn; p.K[z] = Cn; p.act[z] = 0; p.rnd[z] = 0; }
        gemm3<128, 128, 64, 32><<<dim3(16, 16, 3), 256, smemA>>>(p);
    }

    // 3a) LoRA ups on side stream (padded N: 128,128,64,256)
    {
        GB p = {};
        p.A[0] = p_xw; p.A[1] = p_xa; p.A[2] = p_xv; p.A[3] = p_xg;
        p.Bw[0] = p_w1; p.Bw[1] = p_a1; p.Bw[2] = p_v1; p.Bw[3] = p_g1;
        p.C[0] = p_tw; p.C[1] = p_ta; p.C[2] = p_tv; p.C[3] = p_tg;
        p.N[0] = 128; p.N[1] = 128; p.N[2] = 64; p.N[3] = 256;
        for (int z = 0; z < 4; z++) { p.K[z] = Cn; p.rnd[z] = 1; }
        p.act[0] = 1; p.act[1] = 0; p.act[2] = 0; p.act[3] = 2;
        gemm3<128, 64, 64, 32><<<dim3(4, 16, 4), 128, smemUp, s1>>>(p);
    }

    // 3b) LoRA downs on side stream (K padded to 128 for w/a; zero rows)
    {
        GB p = {};
        p.A[0] = p_tw; p.A[1] = p_ta; p.A[2] = p_tv; p.A[3] = p_tg;
        p.Bw[0] = p_w2; p.Bw[1] = p_a2; p.Bw[2] = p_v2; p.Bw[3] = p_g2;
        p.C[0] = p_w;  p.C[1] = p_za; p.C[2] = p_zv; p.C[3] = p_g;
        p.K[0] = 128; p.K[1] = 128; p.K[2] = 64; p.K[3] = 256;
        for (int z = 0; z < 4; z++) { p.N[z] = Cn; p.act[z] = 0; p.rnd[z] = 0; }
        gemm3<128, 128, 64, 32><<<dim3(16, 16, 4), 256, smemA, s1>>>(p);
    }

    // join
    cudaEventRecord(evJoin, s1);
    cudaStreamWaitEvent(0, evJoin, 0);

    // 4) per-head elementwise -> packed scan operands
    ew2_kernel<<<BTn * Hn / 8, 256>>>(w0, a0, v0, k_k, k_a, vfirst);

    // 5) WKV7 scan
    wkv7_scan<<<2 * Bn * Hn, 128>>>();

    // 6) groupnorm + residual + gate
    gn_kernel<<<BTn * Hn / 8, 256>>>(r_k, gnw, gnb);

    // 7) output projection
    {
        GB p = {};
        p.A[0] = p_op; p.Bw[0] = p_Wo; p.C[0] = out;
        p.N[0] = Cn; p.K[0] = Cn; p.act[0] = 0; p.rnd[0] = 0;
        gemm3<128, 128, 64, 32><<<dim3(16, 16, 1), 256, smemA>>>(p);
    }
}

// round 9
// speedup vs baseline: 5.4417x; 1.1358x over previous
#include <cuda_runtime.h>
#include <math.h>

// Problem constants
#define Bn 2
#define Tn 1024
#define Cn 2048
#define Hn 32
#define Nn 64
#define BTn (Bn*Tn)

// ------------------------- scratch (static device globals) -------------------------
__device__ float g_xr[BTn*Cn];
__device__ float g_xw[BTn*Cn];
__device__ float g_xk[BTn*Cn];
__device__ float g_xv[BTn*Cn];
__device__ float g_xa[BTn*Cn];
__device__ float g_xg[BTn*Cn];
__device__ float g_r [BTn*Cn];
__device__ float g_k [BTn*Cn];
__device__ float g_v [BTn*Cn];
__device__ float g_w [BTn*Cn];
__device__ float g_za[BTn*Cn];
__device__ float g_zv[BTn*Cn];
__device__ float g_g [BTn*Cn];
__device__ float g_y [BTn*Cn];
__device__ float g_op[BTn*Cn];
__device__ float g_tw[BTn*128];   // padded 96->128
__device__ float g_ta[BTn*128];   // padded 96->128
__device__ float g_tv[BTn*64];
__device__ float g_tg[BTn*256];
// packed scan operands: [B*H][T][6*64]  order: r,w,k,v,ah,bh
__device__ float g_pack[(size_t)Bn*Hn*Tn*384];
// pre-rounded (tf32) weights
__device__ float g_Wr[Cn*Cn];
__device__ float g_Wk[Cn*Cn];
__device__ float g_Wv[Cn*Cn];
__device__ float g_Wo[Cn*Cn];
__device__ float g_w1r[Cn*128];
__device__ float g_a1r[Cn*128];
__device__ float g_v1r[Cn*64];
__device__ float g_g1r[Cn*256];
__device__ float g_w2r[128*Cn];
__device__ float g_a2r[128*Cn];
__device__ float g_v2r[64*Cn];
__device__ float g_g2r[256*Cn];

// ------------------------- helpers -------------------------
__device__ __forceinline__ unsigned f2tf32(float f) {
    unsigned u;
    asm("cvt.rna.tf32.f32 %0, %1;" : "=r"(u) : "f"(f));
    return u;
}
__device__ __forceinline__ float rnd_tf32(float f) { return __uint_as_float(f2tf32(f)); }

__device__ __forceinline__ void mma_tf32(float* d, const unsigned* a, const unsigned* b) {
    asm volatile(
        "mma.sync.aligned.m16n8k8.row.col.f32.tf32.tf32.f32 "
        "{%0,%1,%2,%3}, {%4,%5,%6,%7}, {%8,%9}, {%0,%1,%2,%3};"
        : "+f"(d[0]), "+f"(d[1]), "+f"(d[2]), "+f"(d[3])
        : "r"(a[0]), "r"(a[1]), "r"(a[2]), "r"(a[3]),
          "r"(b[0]), "r"(b[1]));
}

__device__ __forceinline__ void cp16(void* smem, const void* g) {
    unsigned saddr = (unsigned)__cvta_generic_to_shared(smem);
    asm volatile("cp.async.cg.shared.global [%0], [%1], 16;" :: "r"(saddr), "l"(g));
}
__device__ __forceinline__ void cp_commit() { asm volatile("cp.async.commit_group;" ::: "memory"); }
__device__ __forceinline__ void cp_wait1()  { asm volatile("cp.async.wait_group 1;" ::: "memory"); }

__device__ __forceinline__ float warp_sum(float v) {
#pragma unroll
    for (int o = 16; o > 0; o >>= 1) v += __shfl_xor_sync(0xffffffffu, v, o);
    return v;
}

// ------------------------- weight rounding prepass -------------------------
struct RP {
    const float4* src[8];
    float4* dst[8];
    int n4[8];
};
__global__ void round_weights(RP p) {
    int zb = blockIdx.y;
    int i = blockIdx.x * blockDim.x + threadIdx.x;
    if (i >= p.n4[zb]) return;
    float4 v = p.src[zb][i];
    v.x = rnd_tf32(v.x); v.y = rnd_tf32(v.y);
    v.z = rnd_tf32(v.z); v.w = rnd_tf32(v.w);
    p.dst[zb][i] = v;
}

struct PP {
    const float* src[4];
    float* dst[4];
    int dstR[4], dstC[4], srcR[4], srcC[4];
};
__global__ void pad_weights(PP p) {
    int zb = blockIdx.y;
    int i = blockIdx.x * blockDim.x + threadIdx.x;
    int tot = p.dstR[zb] * p.dstC[zb];
    if (i >= tot) return;
    int r = i / p.dstC[zb], c = i % p.dstC[zb];
    float v = 0.f;
    if (r < p.srcR[zb] && c < p.srcC[zb])
        v = rnd_tf32(p.src[zb][r * p.srcC[zb] + c]);
    p.dst[zb][i] = v;
}

// ------------------------- batched 3-stage tf32 GEMM (pre-rounded operands) --------
struct GB {
    const float* A[4];
    const float* Bw[4];
    float*       C[4];
    int N[4];
    int K[4];
    int act[4];   // 0=none 1=tanh 2=sigmoid
    int rnd[4];   // round output to tf32?
};

template<int BM, int BN, int WM, int WN>
__global__ void __launch_bounds__((BM/WM)*(BN/WN)*32)
gemm3(GB p) {
    constexpr int KT = 16;
    constexpr int STG = 3;
    constexpr int WARPS_M = BM / WM;
    constexpr int WARPS_N = BN / WN;
    constexpr int NTHREADS = WARPS_M * WARPS_N * 32;
    constexpr int MT = WM / 16;
    constexpr int NT_ = WN / 8;
    constexpr int ASTR = KT + 4;
    constexpr int BSTR = BN + 8;

    extern __shared__ unsigned dsm[];
    unsigned (*Asm)[BM][ASTR] = (unsigned(*)[BM][ASTR])dsm;
    unsigned (*Bsm)[KT][BSTR] = (unsigned(*)[KT][BSTR])(dsm + STG * BM * ASTR);

    const int z = blockIdx.z;
    const float* A = p.A[z];
    const float* B = p.Bw[z];
    float* C = p.C[z];
    const int N = p.N[z], K = p.K[z], act = p.act[z], rd = p.rnd[z];
    const int bn = blockIdx.x * BN;
    if (bn >= N) return;
    const int bm = blockIdx.y * BM;

    const int tid = threadIdx.x;
    const int wid = tid >> 5, lane = tid & 31;
    const int gid = lane >> 2, tig = lane & 3;
    const int warp_m = wid / WARPS_N, warp_n = wid % WARPS_N;
    const int wm = warp_m * WM, wn = warp_n * WN;

    float acc[MT][NT_][4];
#pragma unroll
    for (int i = 0; i < MT; i++)
#pragma unroll
        for (int j = 0; j < NT_; j++)
#pragma unroll
            for (int q = 0; q < 4; q++) acc[i][j][q] = 0.f;

    auto load_stage = [&](int s, int k0) {
#pragma unroll
        for (int i = 0; i < (BM * 4) / NTHREADS; i++) {
            int id = tid + i * NTHREADS;
            int m = id >> 2, kc = (id & 3) * 4;
            cp16(&Asm[s][m][kc], A + (size_t)(bm + m) * K + k0 + kc);
        }
#pragma unroll
        for (int i = 0; i < (KT * BN / 4) / NTHREADS; i++) {
            int id = tid + i * NTHREADS;
            int kr = id / (BN / 4), nq = (id % (BN / 4)) * 4;
            cp16(&Bsm[s][kr][nq], B + (size_t)(k0 + kr) * N + bn + nq);
        }
    };

    const int nk = K / KT;
    load_stage(0, 0); cp_commit();
    load_stage(1, KT); cp_commit();

    int s = 0;
    for (int kt = 0; kt < nk; kt++) {
        cp_wait1();
        __syncthreads();
        if (kt + 2 < nk) load_stage((kt + 2) % STG, (kt + 2) * KT);
        cp_commit();

#pragma unroll
        for (int kk = 0; kk < KT; kk += 8) {
            unsigned af[MT][4], bf[NT_][2];
#pragma unroll
            for (int mt = 0; mt < MT; mt++) {
                int rm = wm + mt * 16 + gid;
                af[mt][0] = Asm[s][rm][kk + tig];
                af[mt][1] = Asm[s][rm + 8][kk + tig];
                af[mt][2] = Asm[s][rm][kk + tig + 4];
                af[mt][3] = Asm[s][rm + 8][kk + tig + 4];
            }
#pragma unroll
            for (int nt = 0; nt < NT_; nt++) {
                int cn = wn + nt * 8 + gid;
                bf[nt][0] = Bsm[s][kk + tig][cn];
                bf[nt][1] = Bsm[s][kk + tig + 4][cn];
            }
#pragma unroll
            for (int mt = 0; mt < MT; mt++)
#pragma unroll
                for (int nt = 0; nt < NT_; nt++)
                    mma_tf32(acc[mt][nt], af[mt], bf[nt]);
        }
        s = (s + 1 == STG) ? 0 : s + 1;
    }

#pragma unroll
    for (int mt = 0; mt < MT; mt++) {
#pragma unroll
        for (int nt = 0; nt < NT_; nt++) {
            int r0 = bm + wm + mt * 16 + gid;
            int c = bn + wn + nt * 8 + tig * 2;
            float v0 = acc[mt][nt][0], v1 = acc[mt][nt][1];
            float v2 = acc[mt][nt][2], v3 = acc[mt][nt][3];
            if (act == 1) {
                v0 = tanhf(v0); v1 = tanhf(v1); v2 = tanhf(v2); v3 = tanhf(v3);
            } else if (act == 2) {
                v0 = 1.f / (1.f + expf(-v0)); v1 = 1.f / (1.f + expf(-v1));
                v2 = 1.f / (1.f + expf(-v2)); v3 = 1.f / (1.f + expf(-v3));
            }
            if (rd) {
                v0 = rnd_tf32(v0); v1 = rnd_tf32(v1);
                v2 = rnd_tf32(v2); v3 = rnd_tf32(v3);
            }
            *(float2*)(C + (size_t)r0 * N + c) = make_float2(v0, v1);
            *(float2*)(C + (size_t)(r0 + 8) * N + c) = make_float2(v2, v3);
        }
    }
}

// ------------------------- token shift + 6 mixes (float4, tf32-rounded out) --------
__global__ void mix_kernel(const float4* __restrict__ x,
                           const float4* __restrict__ cr, const float4* __restrict__ cw,
                           const float4* __restrict__ ck, const float4* __restrict__ cv,
                           const float4* __restrict__ ca, const float4* __restrict__ cg) {
    size_t i = (size_t)blockIdx.x * blockDim.x + threadIdx.x;
    constexpr size_t TOT = (size_t)BTn * Cn / 4;
    constexpr int C4 = Cn / 4;
    if (i >= TOT) return;
    int c = (int)(i % C4);
    size_t bt = i / C4;
    int t = (int)(bt % Tn);
    float4 xc = x[i];
    float4 prev = (t == 0) ? make_float4(0.f, 0.f, 0.f, 0.f) : x[i - C4];
    float4 dx = make_float4(prev.x - xc.x, prev.y - xc.y, prev.z - xc.z, prev.w - xc.w);
#define MIXO(dst, coef) { \
    float4 cc = coef[c]; \
    ((float4*)dst)[i] = make_float4( \
        rnd_tf32(fmaf(dx.x, cc.x, xc.x)), rnd_tf32(fmaf(dx.y, cc.y, xc.y)), \
        rnd_tf32(fmaf(dx.z, cc.z, xc.z)), rnd_tf32(fmaf(dx.w, cc.w, xc.w))); }
    MIXO(g_xr, cr); MIXO(g_xw, cw); MIXO(g_xk, ck);
    MIXO(g_xv, cv); MIXO(g_xa, ca); MIXO(g_xg, cg);
#undef MIXO
}

// ------------------------- per-head elementwise stage 2 (warp per head) -----------
__global__ void __launch_bounds__(256) ew2_kernel(
        const float* __restrict__ w0, const float* __restrict__ a0,
        const float* __restrict__ v0, const float* __restrict__ kkw,
        const float* __restrict__ kaw, const float* __restrict__ vfirst) {
    int w = blockIdx.x * 8 + (threadIdx.x >> 5);
    int lane = threadIdx.x & 31;
    int bt = w / Hn, h = w % Hn;
    int b = bt / Tn, t = bt % Tn;
    size_t pb = ((size_t)(b * Hn + h) * Tn + t) * 384;
    size_t base = (size_t)bt * Cn + h * Nn;

    float kraw[2], kkp[2], av[2], vv[2], wv[2];
#pragma unroll
    for (int j = 0; j < 2; j++) {
        int n = lane + 32 * j;
        int c = h * Nn + n;
        size_t idx = base + n;
        kraw[j] = g_k[idx];
        kkp[j] = kraw[j] * kkw[c];
        av[j] = 1.f / (1.f + expf(-(a0[c] + g_za[idx])));
        float xw = -(w0[c] + g_w[idx]);
        float sp = (xw > 20.f) ? xw : log1pf(expf(xw));
        wv[j] = expf(-expf(-0.5f - sp));
        float vs = 1.f / (1.f + expf(-(v0[c] + g_zv[idx])));
        float vraw = g_v[idx];
        vv[j] = vraw + (vfirst[idx] - vraw) * vs;
    }
    float nrm2 = warp_sum(kkp[0] * kkp[0] + kkp[1] * kkp[1]);
    float inv = 1.f / fmaxf(sqrtf(nrm2), 1e-12f);

#pragma unroll
    for (int j = 0; j < 2; j++) {
        int n = lane + 32 * j;
        int c = h * Nn + n;
        size_t idx = base + n;
        float kkn = kkp[j] * inv;
        g_pack[pb +       n] = g_r[idx];
        g_pack[pb +  64 + n] = wv[j];
        g_pack[pb + 128 + n] = kraw[j] * (1.f + (av[j] - 1.f) * kaw[c]);
        g_pack[pb + 192 + n] = vv[j];
        g_pack[pb + 256 + n] = -kkn;
        g_pack[pb + 320 + n] = kkn * av[j];
    }
}

// ------------------------- WKV7 scan: 8-step groups, cp.async prefetch ------------
__global__ void __launch_bounds__(128) wkv7_scan() {
    const int bh = blockIdx.x >> 1;
    const int vh = blockIdx.x & 1;
    const int b = bh / Hn, h = bh % Hn;
    const int tid = threadIdx.x;
    const int v_local = tid >> 2;
    const int kq = tid & 3;
    const int v = vh * 32 + v_local;
    constexpr int GS = 8;

    float S[16];
#pragma unroll
    for (int i = 0; i < 16; i++) S[i] = 0.f;

    __shared__ float4 sm4[2][GS][96];
    const float4* pk4 = (const float4*)(g_pack + (size_t)bh * Tn * 384);
    size_t ybase = (size_t)b * Tn * Cn + (size_t)h * Nn + v;

    auto load_group = [&](int buf, int g) {
#pragma unroll
        for (int i = 0; i < (GS * 96) / 128; i++) {
            int id = tid + i * 128;
            int st = id / 96, off = id % 96;
            cp16(&sm4[buf][st][off], pk4 + (size_t)(g * GS + st) * 96 + off);
        }
    };

    load_group(0, 0); cp_commit();
    load_group(1, 1); cp_commit();

    const int kb4 = kq * 4;
    constexpr int NG = Tn / GS;

    for (int g = 0; g < NG; g++) {
        cp_wait1();
        __syncthreads();
        const int buf = g & 1;

#pragma unroll
        for (int st = 0; st < GS; st++) {
            const float4* r4  = &sm4[buf][st][0  + kb4];
            const float4* w4  = &sm4[buf][st][16 + kb4];
            const float4* k4  = &sm4[buf][st][32 + kb4];
            const float4* ah4 = &sm4[buf][st][64 + kb4];
            const float4* bh4 = &sm4[buf][st][80 + kb4];
            const float vv = ((const float*)&sm4[buf][st][48])[v];

            float4 A0 = ah4[0], A1 = ah4[1], A2 = ah4[2], A3 = ah4[3];
            float sa0 = S[0] * A0.x, sa1 = S[4] * A1.x, sa2 = S[8] * A2.x, sa3 = S[12] * A3.x;
            sa0 = fmaf(S[1], A0.y, sa0); sa1 = fmaf(S[5], A1.y, sa1);
            sa2 = fmaf(S[9], A2.y, sa2); sa3 = fmaf(S[13], A3.y, sa3);
            sa0 = fmaf(S[2], A0.z, sa0); sa1 = fmaf(S[6], A1.z, sa1);
            sa2 = fmaf(S[10], A2.z, sa2); sa3 = fmaf(S[14], A3.z, sa3);
            sa0 = fmaf(S[3], A0.w, sa0); sa1 = fmaf(S[7], A1.w, sa1);
            sa2 = fmaf(S[11], A2.w, sa2); sa3 = fmaf(S[15], A3.w, sa3);
            float sa = (sa0 + sa1) + (sa2 + sa3);
            sa += __shfl_xor_sync(0xffffffffu, sa, 1);
            sa += __shfl_xor_sync(0xffffffffu, sa, 2);

            float y0 = 0.f, y1 = 0.f, y2 = 0.f, y3 = 0.f;
#pragma unroll
            for (int j = 0; j < 4; j++) {
                float4 W = w4[j], Bv = bh4[j], Kv = k4[j], R = r4[j];
                S[j*4+0] = fmaf(S[j*4+0], W.x, fmaf(sa, Bv.x, vv * Kv.x));
                S[j*4+1] = fmaf(S[j*4+1], W.y, fmaf(sa, Bv.y, vv * Kv.y));
                S[j*4+2] = fmaf(S[j*4+2], W.z, fmaf(sa, Bv.z, vv * Kv.z));
                S[j*4+3] = fmaf(S[j*4+3], W.w, fmaf(sa, Bv.w, vv * Kv.w));
                y0 = fmaf(S[j*4+0], R.x, y0);
                y1 = fmaf(S[j*4+1], R.y, y1);
                y2 = fmaf(S[j*4+2], R.z, y2);
                y3 = fmaf(S[j*4+3], R.w, y3);
            }
            float y = (y0 + y1) + (y2 + y3);
            y += __shfl_xor_sync(0xffffffffu, y, 1);
            y += __shfl_xor_sync(0xffffffffu, y, 2);
            if (kq == 0) g_y[ybase + (size_t)(g * GS + st) * Cn] = y;
        }

        __syncthreads();
        if (g + 2 < NG) load_group(buf, g + 2);
        cp_commit();
    }
}

// ------------------------- groupnorm + rk residual + gate (warp per head) ---------
__global__ void __launch_bounds__(256) gn_kernel(
        const float* __restrict__ r_k, const float* __restrict__ gnw,
        const float* __restrict__ gnb) {
    int w = blockIdx.x * 8 + (threadIdx.x >> 5);
    int lane = threadIdx.x & 31;
    int bt = w / Hn, h = w % Hn;
    int b = bt / Tn, t = bt % Tn;
    size_t pb = ((size_t)(b * Hn + h) * Tn + t) * 384;
    size_t base = (size_t)bt * Cn + h * Nn;

    float yv[2], rr[2], kk[2], vv[2];
#pragma unroll
    for (int j = 0; j < 2; j++) {
        int n = lane + 32 * j;
        yv[j] = g_y[base + n];
        rr[j] = g_pack[pb + n];
        kk[j] = g_pack[pb + 128 + n];
        vv[j] = g_pack[pb + 192 + n];
    }
    float mu = warp_sum(yv[0] + yv[1]) * (1.f / 64.f);
    float d0 = yv[0] - mu, d1 = yv[1] - mu;
    float var = warp_sum(d0 * d0 + d1 * d1) * (1.f / 64.f);
    float rs = rsqrtf(var + (float)(Nn * 1e-5));

    float dp0, dp1;
    {
        int c0 = h * Nn + lane, c1 = c0 + 32;
        dp0 = rr[0] * kk[0] * r_k[c0];
        dp1 = rr[1] * kk[1] * r_k[c1];
    }
    float dot = warp_sum(dp0 + dp1);

#pragma unroll
    for (int j = 0; j < 2; j++) {
        int n = lane + 32 * j;
        int c = h * Nn + n;
        size_t idx = base + n;
        float d = (j == 0) ? d0 : d1;
        float yn = d * rs * gnw[c] + gnb[c];
        g_op[idx] = rnd_tf32((yn + dot * vv[j]) * g_g[idx]);
    }
}

// ------------------------- launch -------------------------
extern "C" void kernel_launch(void* const* d_in, const int* in_sizes, int n_in,
                              void* d_out, int out_size) {
    (void)in_sizes; (void)n_in; (void)out_size;
    const float* x      = (const float*)d_in[0];
    const float* vfirst = (const float*)d_in[1];
    const float* x_r = (const float*)d_in[2];
    const float* x_w = (const float*)d_in[3];
    const float* x_k = (const float*)d_in[4];
    const float* x_v = (const float*)d_in[5];
    const float* x_a = (const float*)d_in[6];
    const float* x_g = (const float*)d_in[7];
    const float* w0  = (const float*)d_in[8];
    const float* w1  = (const float*)d_in[9];
    const float* w2  = (const float*)d_in[10];
    const float* a0  = (const float*)d_in[11];
    const float* a1  = (const float*)d_in[12];
    const float* a2  = (const float*)d_in[13];
    const float* v0  = (const float*)d_in[14];
    const float* v1  = (const float*)d_in[15];
    const float* v2  = (const float*)d_in[16];
    const float* g1  = (const float*)d_in[17];
    const float* g2  = (const float*)d_in[18];
    const float* k_k = (const float*)d_in[19];
    const float* k_a = (const float*)d_in[20];
    const float* r_k = (const float*)d_in[21];
    const float* W_r = (const float*)d_in[22];
    const float* W_k = (const float*)d_in[23];
    const float* W_v = (const float*)d_in[24];
    const float* W_o = (const float*)d_in[25];
    const float* gnw = (const float*)d_in[26];
    const float* gnb = (const float*)d_in[27];
    float* out = (float*)d_out;

#define GETP(name, sym) float* name; cudaGetSymbolAddress((void**)&name, sym)
    GETP(p_xr, g_xr); GETP(p_xw, g_xw); GETP(p_xk, g_xk); GETP(p_xv, g_xv);
    GETP(p_xa, g_xa); GETP(p_xg, g_xg);
    GETP(p_r, g_r); GETP(p_k, g_k); GETP(p_v, g_v); GETP(p_w, g_w);
    GETP(p_za, g_za); GETP(p_zv, g_zv); GETP(p_g, g_g); GETP(p_op, g_op);
    GETP(p_tw, g_tw); GETP(p_ta, g_ta); GETP(p_tv, g_tv); GETP(p_tg, g_tg);
    GETP(p_Wr, g_Wr); GETP(p_Wk, g_Wk); GETP(p_Wv, g_Wv); GETP(p_Wo, g_Wo);
    GETP(p_w1, g_w1r); GETP(p_a1, g_a1r); GETP(p_v1, g_v1r); GETP(p_g1, g_g1r);
    GETP(p_w2, g_w2r); GETP(p_a2, g_a2r); GETP(p_v2, g_v2r); GETP(p_g2, g_g2r);
#undef GETP

    // persistent side stream + events for fork/join under graph capture
    static cudaStream_t s1 = nullptr;
    static cudaEvent_t evFork = nullptr, evW = nullptr, evM = nullptr, evJ = nullptr;
    if (!s1) {
        cudaStreamCreateWithFlags(&s1, cudaStreamNonBlocking);
        cudaEventCreateWithFlags(&evFork, cudaEventDisableTiming);
        cudaEventCreateWithFlags(&evW, cudaEventDisableTiming);
        cudaEventCreateWithFlags(&evM, cudaEventDisableTiming);
        cudaEventCreateWithFlags(&evJ, cudaEventDisableTiming);
    }

    // LEGAL FORK: event originates on the capturing (main) stream, side stream
    // joins the capture by waiting on it BEFORE any launch on s1.
    cudaEventRecord(evFork, 0);
    cudaStreamWaitEvent(s1, evFork, 0);

    // 0) weight rounding prepass on SIDE stream (overlaps with mix on main)
    {
        RP rp = {};
        const float* srcs[8] = {W_r, W_k, W_v, W_o, v1, g1, v2, g2};
        float* dsts[8] = {p_Wr, p_Wk, p_Wv, p_Wo, p_v1, p_g1, p_v2, p_g2};
        int cnt[8] = {Cn*Cn, Cn*Cn, Cn*Cn, Cn*Cn, Cn*64, Cn*256, 64*Cn, 256*Cn};
        int maxn4 = 0;
        for (int i = 0; i < 8; i++) {
            rp.src[i] = (const float4*)srcs[i];
            rp.dst[i] = (float4*)dsts[i];
            rp.n4[i] = cnt[i] / 4;
            if (rp.n4[i] > maxn4) maxn4 = rp.n4[i];
        }
        round_weights<<<dim3((maxn4 + 255) / 256, 8), 256, 0, s1>>>(rp);

        PP pp = {};
        const float* psrc[4] = {w1, a1, w2, a2};
        float* pdst[4] = {p_w1, p_a1, p_w2, p_a2};
        int dR[4] = {Cn, Cn, 128, 128}, dC[4] = {128, 128, Cn, Cn};
        int sR[4] = {Cn, Cn, 96, 96},   sC[4] = {96, 96, Cn, Cn};
        int maxt = 0;
        for (int i = 0; i < 4; i++) {
            pp.src[i] = psrc[i]; pp.dst[i] = pdst[i];
            pp.dstR[i] = dR[i]; pp.dstC[i] = dC[i];
            pp.srcR[i] = sR[i]; pp.srcC[i] = sC[i];
            if (dR[i] * dC[i] > maxt) maxt = dR[i] * dC[i];
        }
        pad_weights<<<dim3((maxt + 255) / 256, 4), 256, 0, s1>>>(pp);
        cudaEventRecord(evW, s1);
    }

    // 1) token shift + mixes on MAIN
    mix_kernel<<<(BTn * Cn / 4 + 255) / 256, 256>>>(
        (const float4*)x, (const float4*)x_r, (const float4*)x_w, (const float4*)x_k,
        (const float4*)x_v, (const float4*)x_a, (const float4*)x_g);
    cudaEventRecord(evM, 0);

    // main waits for weights; side waits for mix
    cudaStreamWaitEvent(0, evW, 0);
    cudaStreamWaitEvent(s1, evM, 0);

    constexpr int KT = 16, STG = 3;
    const int smemA  = STG * (128 * (KT + 4) + KT * (128 + 8)) * 4;   // 56832
    const int smemUp = STG * (128 * (KT + 4) + KT * (64 + 8)) * 4;    // 44544
    cudaFuncSetAttribute(gemm3<128, 128, 64, 64>,
                         cudaFuncAttributeMaxDynamicSharedMemorySize, smemA);
    cudaFuncSetAttribute(gemm3<128, 64, 64, 32>,
                         cudaFuncAttributeMaxDynamicSharedMemorySize, smemUp);

    // 2) r/k/v projections (main stream) — 64x64 warp tiles, 128 threads
    {
        GB p = {};
        p.A[0] = p_xr; p.A[1] = p_xk; p.A[2] = p_xv;
        p.Bw[0] = p_Wr; p.Bw[1] = p_Wk; p.Bw[2] = p_Wv;
        p.C[0] = p_r;  p.C[1] = p_k;  p.C[2] = p_v;
        for (int z = 0; z < 3; z++) { p.N[z] = Cn; p.K[z] = Cn; p.act[z] = 0; p.rnd[z] = 0; }
        gemm3<128, 128, 64, 64><<<dim3(16, 16, 3), 128, smemA>>>(p);
    }

    // 3a) LoRA ups on side stream
    {
        GB p = {};
        p.A[0] = p_xw; p.A[1] = p_xa; p.A[2] = p_xv; p.A[3] = p_xg;
        p.Bw[0] = p_w1; p.Bw[1] = p_a1; p.Bw[2] = p_v1; p.Bw[3] = p_g1;
        p.C[0] = p_tw; p.C[1] = p_ta; p.C[2] = p_tv; p.C[3] = p_tg;
        p.N[0] = 128; p.N[1] = 128; p.N[2] = 64; p.N[3] = 256;
        for (int z = 0; z < 4; z++) { p.K[z] = Cn; p.rnd[z] = 1; }
        p.act[0] = 1; p.act[1] = 0; p.act[2] = 0; p.act[3] = 2;
        gemm3<128, 64, 64, 32><<<dim3(4, 16, 4), 128, smemUp, s1>>>(p);
    }

    // 3b) LoRA downs on side stream
    {
        GB p = {};
        p.A[0] = p_tw; p.A[1] = p_ta; p.A[2] = p_tv; p.A[3] = p_tg;
        p.Bw[0] = p_w2; p.Bw[1] = p_a2; p.Bw[2] = p_v2; p.Bw[3] = p_g2;
        p.C[0] = p_w;  p.C[1] = p_za; p.C[2] = p_zv; p.C[3] = p_g;
        p.K[0] = 128; p.K[1] = 128; p.K[2] = 64; p.K[3] = 256;
        for (int z = 0; z < 4; z++) { p.N[z] = Cn; p.act[z] = 0; p.rnd[z] = 0; }
        gemm3<128, 128, 64, 64><<<dim3(16, 16, 4), 128, smemA, s1>>>(p);
    }

    // join
    cudaEventRecord(evJ, s1);
    cudaStreamWaitEvent(0, evJ, 0);

    // 4) per-head elementwise -> packed scan operands
    ew2_kernel<<<BTn * Hn / 8, 256>>>(w0, a0, v0, k_k, k_a, vfirst);

    // 5) WKV7 scan
    wkv7_scan<<<2 * Bn * Hn, 128>>>();

    // 6) groupnorm + residual + gate
    gn_kernel<<<BTn * Hn / 8, 256>>>(r_k, gnw, gnb);

    // 7) output projection
    {
        GB p = {};
        p.A[0] = p_op; p.Bw[0] = p_Wo; p.C[0] = out;
        p.N[0] = Cn; p.K[0] = Cn; p.act[0] = 0; p.rnd[0] = 0;
        gemm3<128, 128, 64, 64><<<dim3(16, 16, 1), 128, smemA>>>(p);
    }
}